// round 11
// baseline (speedup 1.0000x reference)
#include <cuda_runtime.h>
#include <cuda_bf16.h>
#include <cuda_fp16.h>
#include <cstdint>

#define B_TOK 8192
#define IN_DIM 512
#define HID 2048
#define NCLS 1000
#define NCLS_PAD 1024
#define NEXP 4
#define RH 256
#define RH2 128

// s8 encodings for ternary values
#define S8_P1 0x01u
#define S8_M1 0xFFu

// ------------------------- scratch (device globals; no allocation) -------------------------
__device__ __half         d_h[(size_t)NEXP * B_TOK * HID];        // h1 / h2 / eo (fp16, exact ints)
__device__ uint8_t        d_s[(size_t)NEXP * B_TOK * HID];        // s8 sign activations {0,1}
__device__ uint8_t        d_w1t[(size_t)NEXP * HID * IN_DIM];     // s8 ternary weights
__device__ uint8_t        d_w2t[(size_t)NEXP * HID * HID];
__device__ uint8_t        d_w3t[(size_t)NEXP * NCLS_PAD * HID];
__device__ uint8_t        d_xse[(size_t)NEXP * B_TOK * IN_DIM];   // per-expert compacted sign(x) s8
__device__ __nv_bfloat16  d_xsplit[(size_t)B_TOK * IN_DIM * 3];   // split-3 x (router)
__device__ __nv_bfloat16  d_wr1s[(size_t)RH * IN_DIM * 3];
__device__ __nv_bfloat16  d_wr2s[(size_t)RH2 * RH * 3];
__device__ __nv_bfloat16  d_r1s[(size_t)B_TOK * RH * 3];          // split-3 relu(layer1)
__device__ float          d_r2[(size_t)B_TOK * RH2];
__device__ float2         d_gates[B_TOK];
__device__ int2           d_sel[B_TOK];
__device__ int2           d_pos[B_TOK];
__device__ int            d_cnt[NEXP];
__device__ int            d_padcnt[NEXP];
__device__ int            d_idx[NEXP * B_TOK];
__device__ float          d_wpart[NEXP * 256];
__device__ float          d_wmean[12];

// ------------------------- weight prep -------------------------

__global__ void wsum_partial(const float* __restrict__ W, float* __restrict__ part, long n4) {
    const int e = blockIdx.y;
    const float4* w = (const float4*)W + (size_t)e * n4;
    float s = 0.f;
    for (long i = (long)blockIdx.x * blockDim.x + threadIdx.x; i < n4;
         i += (long)gridDim.x * blockDim.x) {
        float4 v = w[i];
        s += (v.x + v.y) + (v.z + v.w);
    }
    __shared__ float sh[256];
    sh[threadIdx.x] = s;
    __syncthreads();
    for (int st = 128; st; st >>= 1) {
        if (threadIdx.x < st) sh[threadIdx.x] += sh[threadIdx.x + st];
        __syncthreads();
    }
    if (threadIdx.x == 0) part[e * gridDim.x + blockIdx.x] = sh[0];
}

__global__ void wmean_final(const float* __restrict__ part, float* __restrict__ mean,
                            long n, int nb) {
    const int e = blockIdx.x;
    __shared__ float sh[256];
    sh[threadIdx.x] = (threadIdx.x < nb) ? part[e * nb + threadIdx.x] : 0.f;
    __syncthreads();
    for (int st = 128; st; st >>= 1) {
        if (threadIdx.x < st) sh[threadIdx.x] += sh[threadIdx.x + st];
        __syncthreads();
    }
    if (threadIdx.x == 0) mean[e] = sh[0] / (float)n;
}

__global__ void ternarize_s8(const float* __restrict__ W, const float* __restrict__ mean,
                             uint8_t* __restrict__ out, int in_rows, int out_rows, int cols) {
    const int e = blockIdx.y;
    const long n4 = (long)out_rows * cols / 4;
    long i = (long)blockIdx.x * blockDim.x + threadIdx.x;
    if (i >= n4) return;
    const long base = i * 4;
    const int r = (int)(base / cols), c = (int)(base % cols);
    uint32_t v = 0;
    if (r < in_rows) {
        const float m = mean[e];
        const float4 w = *(const float4*)(W + (size_t)e * in_rows * cols + (size_t)r * cols + c);
        const float d0 = w.x - m, d1 = w.y - m, d2 = w.z - m, d3 = w.w - m;
        v  = (d0 > 0.f ? S8_P1 : (d0 < 0.f ? S8_M1 : 0u));
        v |= (d1 > 0.f ? S8_P1 : (d1 < 0.f ? S8_M1 : 0u)) << 8;
        v |= (d2 > 0.f ? S8_P1 : (d2 < 0.f ? S8_M1 : 0u)) << 16;
        v |= (d3 > 0.f ? S8_P1 : (d3 < 0.f ? S8_M1 : 0u)) << 24;
    }
    *(uint32_t*)(out + (size_t)e * out_rows * cols + base) = v;
}

// ------------------------- split-3 fp32->bf16 (router; err ~2^-16) -------------------------

__device__ __forceinline__ void split3_store_A(__nv_bfloat16* o, float v) {
    __nv_bfloat16 h = __float2bfloat16(v);
    float r = v - __bfloat162float(h);
    __nv_bfloat16 m = __float2bfloat16(r);
    o[0] = h; o[1] = m; o[2] = h;
}

__global__ void split3A_kernel(const float* __restrict__ in, __nv_bfloat16* __restrict__ out, long n) {
    long i = (long)blockIdx.x * blockDim.x + threadIdx.x;
    if (i < n) split3_store_A(out + 3 * i, in[i]);
}

__global__ void split3B_kernel(const float* __restrict__ in, __nv_bfloat16* __restrict__ out, long n) {
    long i = (long)blockIdx.x * blockDim.x + threadIdx.x;
    if (i < n) {
        float v = in[i];
        __nv_bfloat16 h = __float2bfloat16(v);
        float r = v - __bfloat162float(h);
        __nv_bfloat16 m = __float2bfloat16(r);
        __nv_bfloat16* o = out + 3 * i;
        o[0] = h; o[1] = h; o[2] = m;
    }
}

// ------------------------- mma / ldmatrix / cp.async helpers -------------------------

__device__ __forceinline__ void mma_bf16(float* c, const uint32_t* a, const uint32_t* b) {
    asm volatile(
        "mma.sync.aligned.m16n8k16.row.col.f32.bf16.bf16.f32 "
        "{%0,%1,%2,%3}, {%4,%5,%6,%7}, {%8,%9}, {%0,%1,%2,%3};\n"
        : "+f"(c[0]), "+f"(c[1]), "+f"(c[2]), "+f"(c[3])
        : "r"(a[0]), "r"(a[1]), "r"(a[2]), "r"(a[3]), "r"(b[0]), "r"(b[1]));
}

// int8 IMMA: native legacy-pipe tensor op (since sm_75); s32 accumulate (exact)
__device__ __forceinline__ void mma_s8(int* c, const uint32_t* a, const uint32_t* b) {
    asm volatile(
        "mma.sync.aligned.m16n8k32.row.col.s32.s8.s8.s32 "
        "{%0,%1,%2,%3}, {%4,%5,%6,%7}, {%8,%9}, {%0,%1,%2,%3};\n"
        : "+r"(c[0]), "+r"(c[1]), "+r"(c[2]), "+r"(c[3])
        : "r"(a[0]), "r"(a[1]), "r"(a[2]), "r"(a[3]), "r"(b[0]), "r"(b[1]));
}

__device__ __forceinline__ void ldsm4(uint32_t* r, uint32_t addr) {
    asm volatile("ldmatrix.sync.aligned.m8n8.x4.shared.b16 {%0,%1,%2,%3}, [%4];"
                 : "=r"(r[0]), "=r"(r[1]), "=r"(r[2]), "=r"(r[3]) : "r"(addr));
}

__device__ __forceinline__ void cp16(uint32_t smem, const void* gmem) {
    asm volatile("cp.async.cg.shared.global [%0], [%1], 16;\n" :: "r"(smem), "l"(gmem));
}
__device__ __forceinline__ void cp_commit() { asm volatile("cp.async.commit_group;\n"); }
template <int N>
__device__ __forceinline__ void cp_wait() {
    asm volatile("cp.async.wait_group %0;\n" :: "n"(N));
}

// ------------------------- INT8 tensor-core GEMM (experts; exact ternary) -------------------------
// C[M,N] = A[M,K] @ B[N,K]^T, s8 operands, s32 accum, fp16 store (exact ints <= 2048).
// Block 128x256x64, 4-stage cp.async, 8 warps (2x4), warp tile 64x64.
// smem 64B rows, swizzle chunk16 ^= (row>>1)&3 (conflict-free, XOR-linear in ks).

#define NSTG 4
#define ATB (128 * 64)
#define BTB (256 * 64)
#define STGB (ATB + BTB)
#define S8_SMEM (NSTG * STGB)

__global__ void __launch_bounds__(256, 1) gemm_s8_kernel(
    const uint8_t* __restrict__ A, size_t strideA,
    const uint8_t* __restrict__ Bm, size_t strideB,
    __half* __restrict__ C, size_t strideC,
    int N, int K, const int* __restrict__ mcnt)
{
    extern __shared__ uint8_t smdyn[];
    const int bm = blockIdx.y * 128;
    const int bn = blockIdx.x * 256;
    if (mcnt && bm >= __ldg(&mcnt[blockIdx.z])) return;
    A  += (size_t)blockIdx.z * strideA + (size_t)bm * K;
    Bm += (size_t)blockIdx.z * strideB + (size_t)bn * K;

    const uint32_t smb = (uint32_t)__cvta_generic_to_shared(smdyn);
    const int tid = threadIdx.x;
    const int lane = tid & 31, warp = tid >> 5;
    const int wm = (warp >> 2) * 64, wn = (warp & 3) * 64;
    const int t8 = lane >> 3, r8 = lane & 7;

    // ldsm base offsets (stage 0, ks 0)
    uint32_t aoff[4], boff[4];
#pragma unroll
    for (int mt = 0; mt < 4; mt++) {
        const int row = wm + mt * 16 + (t8 & 1) * 8 + r8;
        const int ch = (t8 >> 1) ^ ((row >> 1) & 3);
        aoff[mt] = smb + row * 64 + ch * 16;
    }
#pragma unroll
    for (int nt2 = 0; nt2 < 4; nt2++) {
        const int row = wn + nt2 * 16 + (t8 >> 1) * 8 + r8;
        const int ch = (t8 & 1) ^ ((row >> 1) & 3);
        boff[nt2] = smb + ATB + row * 64 + ch * 16;
    }

    // global->smem: 6 x 16B per thread per stage (A: 512 chunks, B: 1024 chunks)
    uint32_t dstoff[6];
    const uint8_t* gsrc[6];
#pragma unroll
    for (int i = 0; i < 6; i++) {
        int id = tid + 256 * i;
        if (id < 512) {
            const int row = id >> 2, ch = id & 3;
            dstoff[i] = smb + row * 64 + ((ch ^ ((row >> 1) & 3)) * 16);
            gsrc[i] = A + (size_t)row * K + ch * 16;
        } else {
            id -= 512;
            const int row = id >> 2, ch = id & 3;
            dstoff[i] = smb + ATB + row * 64 + ((ch ^ ((row >> 1) & 3)) * 16);
            gsrc[i] = Bm + (size_t)row * K + ch * 16;
        }
    }

    int acc[4][8][4];
#pragma unroll
    for (int mt = 0; mt < 4; mt++)
#pragma unroll
        for (int nt = 0; nt < 8; nt++)
#pragma unroll
            for (int j = 0; j < 4; j++) acc[mt][nt][j] = 0;

    const int KC = K / 64;

#pragma unroll
    for (int p = 0; p < NSTG - 1; p++) {
        if (p < KC) {
            const uint32_t so = p * STGB;
#pragma unroll
            for (int i = 0; i < 6; i++) cp16(dstoff[i] + so, gsrc[i] + (size_t)p * 64);
        }
        cp_commit();
    }

    for (int c = 0; c < KC; c++) {
        cp_wait<NSTG - 2>();
        __syncthreads();

        const int pf = c + NSTG - 1;
        if (pf < KC) {
            const uint32_t so2 = (pf % NSTG) * STGB;
#pragma unroll
            for (int i = 0; i < 6; i++) cp16(dstoff[i] + so2, gsrc[i] + (size_t)pf * 64);
        }
        cp_commit();

        const uint32_t so = (c % NSTG) * STGB;
#pragma unroll
        for (int ks = 0; ks < 2; ks++) {
            uint32_t af[4][4];
            uint32_t bf[4][4];
#pragma unroll
            for (int mt = 0; mt < 4; mt++)
                ldsm4(af[mt], (aoff[mt] + so) ^ (ks << 5));
#pragma unroll
            for (int nt2 = 0; nt2 < 4; nt2++)
                ldsm4(bf[nt2], (boff[nt2] + so) ^ (ks << 5));
#pragma unroll
            for (int mt = 0; mt < 4; mt++)
#pragma unroll
                for (int nt = 0; nt < 8; nt++)
                    mma_s8(acc[mt][nt], af[mt], &bf[nt >> 1][(nt & 1) * 2]);
        }
    }

    __half* Cz = C + (size_t)blockIdx.z * strideC;
#pragma unroll
    for (int mt = 0; mt < 4; mt++) {
#pragma unroll
        for (int nt = 0; nt < 8; nt++) {
            const int r0 = bm + wm + mt * 16 + (lane >> 2);
            const int cc = bn + wn + nt * 8 + (lane & 3) * 2;
            *(__half2*)(Cz + (size_t)r0 * N + cc) =
                __floats2half2_rn(__int2float_rn(acc[mt][nt][0]),
                                  __int2float_rn(acc[mt][nt][1]));
            *(__half2*)(Cz + (size_t)(r0 + 8) * N + cc) =
                __floats2half2_rn(__int2float_rn(acc[mt][nt][2]),
                                  __int2float_rn(acc[mt][nt][3]));
        }
    }
}

// ------------------------- bf16 GEMM (router, split-3 exactness) -------------------------
// MODE 1: bias+relu fp32. MODE 2: bias+relu + split3A bf16 store.

template <int MODE>
__global__ void __launch_bounds__(256) gemm_bf16_kernel(
    const __nv_bfloat16* __restrict__ A,
    const __nv_bfloat16* __restrict__ Bm,
    void* __restrict__ Cv,
    int N, int K, const float* __restrict__ bias)
{
    const int bm = blockIdx.y * 128;
    const int bn = blockIdx.x * 64;
    A  += (size_t)bm * K;
    Bm += (size_t)bn * K;

    __shared__ __nv_bfloat16 As[2][128][40];
    __shared__ __nv_bfloat16 Bs[2][64][40];
    const uint32_t ASZ = 128 * 40 * 2, BSZ = 64 * 40 * 2;

    const int tid = threadIdx.x;
    const int lane = tid & 31, warp = tid >> 5;
    const int wm = (warp >> 1) * 32, wn = (warp & 1) * 32;
    const int t8 = lane >> 3, r8 = lane & 7;

    uint32_t aoff[2], boff[2];
#pragma unroll
    for (int mt = 0; mt < 2; mt++) {
        int row = wm + mt * 16 + (t8 & 1) * 8 + r8;
        int col = (t8 >> 1) * 8;
        aoff[mt] = (uint32_t)__cvta_generic_to_shared(&As[0][row][col]);
    }
#pragma unroll
    for (int nt2 = 0; nt2 < 2; nt2++) {
        int row = wn + nt2 * 16 + (t8 >> 1) * 8 + r8;
        int col = (t8 & 1) * 8;
        boff[nt2] = (uint32_t)__cvta_generic_to_shared(&Bs[0][row][col]);
    }

    const int arow = tid >> 2;
    const int acol = (tid & 3) * 8;
    const uint4* ag0 = (const uint4*)(A + (size_t)arow * K) + (tid & 3);
    const uint4* ag1 = (const uint4*)(A + (size_t)(arow + 64) * K) + (tid & 3);
    const uint4* bg  = (const uint4*)(Bm + (size_t)arow * K) + (tid & 3);

    float c[2][4][4];
#pragma unroll
    for (int mt = 0; mt < 2; mt++)
#pragma unroll
        for (int nt = 0; nt < 4; nt++)
#pragma unroll
            for (int j = 0; j < 4; j++) c[mt][nt][j] = 0.f;

    const int KT = K / 32;
    uint4 ra0 = ag0[0], ra1 = ag1[0], rb = bg[0];
    *(uint4*)&As[0][arow][acol]      = ra0;
    *(uint4*)&As[0][arow + 64][acol] = ra1;
    *(uint4*)&Bs[0][arow][acol]      = rb;
    __syncthreads();

    for (int kt = 0; kt < KT; kt++) {
        const int buf = kt & 1;
        if (kt + 1 < KT) {
            ra0 = ag0[(kt + 1) * 4];
            ra1 = ag1[(kt + 1) * 4];
            rb  = bg [(kt + 1) * 4];
        }
#pragma unroll
        for (int ks = 0; ks < 2; ks++) {
            uint32_t af[2][4];
            uint32_t bt[2][4];
#pragma unroll
            for (int mt = 0; mt < 2; mt++)
                ldsm4(af[mt], aoff[mt] + buf * ASZ + ks * 32);
#pragma unroll
            for (int nt2 = 0; nt2 < 2; nt2++)
                ldsm4(bt[nt2], boff[nt2] + buf * BSZ + ks * 32);
#pragma unroll
            for (int mt = 0; mt < 2; mt++)
#pragma unroll
                for (int nt = 0; nt < 4; nt++)
                    mma_bf16(c[mt][nt], af[mt], &bt[nt >> 1][(nt & 1) * 2]);
        }
        if (kt + 1 < KT) {
            *(uint4*)&As[buf ^ 1][arow][acol]      = ra0;
            *(uint4*)&As[buf ^ 1][arow + 64][acol] = ra1;
            *(uint4*)&Bs[buf ^ 1][arow][acol]      = rb;
        }
        __syncthreads();
    }

#pragma unroll
    for (int mt = 0; mt < 2; mt++) {
#pragma unroll
        for (int nt = 0; nt < 4; nt++) {
            const int r0 = bm + wm + mt * 16 + (lane >> 2);
            const int cc = bn + wn + nt * 8 + (lane & 3) * 2;
            const float v00 = c[mt][nt][0], v01 = c[mt][nt][1];
            const float v10 = c[mt][nt][2], v11 = c[mt][nt][3];
            const float b0 = bias[cc], b1 = bias[cc + 1];
            if (MODE == 1) {
                float* C = (float*)Cv;
                C[(size_t)r0 * N + cc]           = fmaxf(v00 + b0, 0.f);
                C[(size_t)r0 * N + cc + 1]       = fmaxf(v01 + b1, 0.f);
                C[(size_t)(r0 + 8) * N + cc]     = fmaxf(v10 + b0, 0.f);
                C[(size_t)(r0 + 8) * N + cc + 1] = fmaxf(v11 + b1, 0.f);
            } else {
                __nv_bfloat16* O = (__nv_bfloat16*)Cv;
                const size_t rs = (size_t)3 * N;
                split3_store_A(O + (size_t)r0 * rs + 3 * cc,       fmaxf(v00 + b0, 0.f));
                split3_store_A(O + (size_t)r0 * rs + 3 * (cc + 1), fmaxf(v01 + b1, 0.f));
                split3_store_A(O + (size_t)(r0 + 8) * rs + 3 * cc,       fmaxf(v10 + b0, 0.f));
                split3_store_A(O + (size_t)(r0 + 8) * rs + 3 * (cc + 1), fmaxf(v11 + b1, 0.f));
            }
        }
    }
}

// ------------------------- LayerNorm + ReLU + sign -> s8 {0,1} -------------------------
__global__ void ln_sign_kernel(const __half* __restrict__ h, const float* __restrict__ g,
                               const float* __restrict__ beta, uint8_t* __restrict__ out,
                               const int* __restrict__ padcnt) {
    const int bt = blockIdx.x;
    const int e = blockIdx.y;
    if (bt >= __ldg(&padcnt[e])) return;
    const size_t base = ((size_t)e * B_TOK + bt) * HID;
    const int tid = threadIdx.x;
    const int o0 = tid * 8;
    const uint4 raw = *(const uint4*)(h + base + o0);
    __half2 p[4];
    p[0] = *(const __half2*)&raw.x;
    p[1] = *(const __half2*)&raw.y;
    p[2] = *(const __half2*)&raw.z;
    p[3] = *(const __half2*)&raw.w;
    float v[8];
#pragma unroll
    for (int j = 0; j < 4; j++) {
        const float2 f = __half22float2(p[j]);
        v[2 * j] = f.x;
        v[2 * j + 1] = f.y;
    }
    float s = 0.f, q = 0.f;
#pragma unroll
    for (int j = 0; j < 8; j++) { s += v[j]; q += v[j] * v[j]; }
#pragma unroll
    for (int off = 16; off; off >>= 1) {
        s += __shfl_xor_sync(0xffffffffu, s, off);
        q += __shfl_xor_sync(0xffffffffu, q, off);
    }
    __shared__ float ss[8], qq[8];
    __shared__ float mu_s, rs_s;
    if ((tid & 31) == 0) { ss[tid >> 5] = s; qq[tid >> 5] = q; }
    __syncthreads();
    if (tid == 0) {
        float S = 0.f, Q = 0.f;
#pragma unroll
        for (int i = 0; i < 8; i++) { S += ss[i]; Q += qq[i]; }
        const float mu = S * (1.f / HID);
        const float var = Q * (1.f / HID) - mu * mu;
        mu_s = mu;
        rs_s = rsqrtf(var + 1e-5f);
    }
    __syncthreads();
    const float mu = mu_s, rs = rs_s;
    const float4 ga0 = *(const float4*)(g + (size_t)e * HID + o0);
    const float4 ga1 = *(const float4*)(g + (size_t)e * HID + o0 + 4);
    const float4 bb0 = *(const float4*)(beta + (size_t)e * HID + o0);
    const float4 bb1 = *(const float4*)(beta + (size_t)e * HID + o0 + 4);
    float y[8];
    y[0] = (v[0] - mu) * rs * ga0.x + bb0.x;
    y[1] = (v[1] - mu) * rs * ga0.y + bb0.y;
    y[2] = (v[2] - mu) * rs * ga0.z + bb0.z;
    y[3] = (v[3] - mu) * rs * ga0.w + bb0.w;
    y[4] = (v[4] - mu) * rs * ga1.x + bb1.x;
    y[5] = (v[5] - mu) * rs * ga1.y + bb1.y;
    y[6] = (v[6] - mu) * rs * ga1.z + bb1.z;
    y[7] = (v[7] - mu) * rs * ga1.w + bb1.w;
    uint32_t lo = 0, hi = 0;
#pragma unroll
    for (int j = 0; j < 4; j++) lo |= (y[j] > 0.f ? S8_P1 : 0u) << (8 * j);
#pragma unroll
    for (int j = 0; j < 4; j++) hi |= (y[4 + j] > 0.f ? S8_P1 : 0u) << (8 * j);
    *(uint2*)(out + base + o0) = make_uint2(lo, hi);
}

// ------------------------- router layer3 + softmax top-2 + gates -------------------------
__global__ void router_top2(const float* __restrict__ r2, const float* __restrict__ Wr3,
                            const float* __restrict__ br3, float2* __restrict__ gates,
                            int2* __restrict__ sel) {
    __shared__ float w[NEXP * RH2];
    __shared__ float bsh[NEXP];
    const int tid = threadIdx.x;
    for (int i = tid; i < NEXP * RH2; i += 256) w[i] = Wr3[i];
    if (tid < NEXP) bsh[tid] = br3[tid];
    __syncthreads();
    const int warp = tid >> 5, lane = tid & 31;
    const int token = blockIdx.x * 8 + warp;
    const float* xr = r2 + (size_t)token * RH2;
    float acc[NEXP] = {0.f, 0.f, 0.f, 0.f};
    for (int k = lane; k < RH2; k += 32) {
        const float xv = xr[k];
#pragma unroll
        for (int e = 0; e < NEXP; e++) acc[e] += xv * w[e * RH2 + k];
    }
#pragma unroll
    for (int e = 0; e < NEXP; e++)
#pragma unroll
        for (int off = 16; off; off >>= 1) acc[e] += __shfl_xor_sync(0xffffffffu, acc[e], off);
    if (lane == 0) {
        float sc[NEXP];
#pragma unroll
        for (int e = 0; e < NEXP; e++) sc[e] = acc[e] + bsh[e];
        int i0 = 0; float v0 = sc[0];
#pragma unroll
        for (int e = 1; e < NEXP; e++) if (sc[e] > v0) { v0 = sc[e]; i0 = e; }
        int i1 = -1; float v1 = -1e30f;
#pragma unroll
        for (int e = 0; e < NEXP; e++) if (e != i0 && sc[e] > v1) { v1 = sc[e]; i1 = e; }
        const float t = expf(v1 - v0);
        const float g0 = 1.f / (1.f + t);
        const float g1 = t / (1.f + t);
        gates[token] = make_float2(g0, g1);
        sel[token] = make_int2(i0, i1);
    }
}

// ------------------------- compaction -------------------------
__global__ void reset_cnt(int* __restrict__ cnt) {
    if (threadIdx.x < NEXP) cnt[threadIdx.x] = 0;
}

__global__ void assign_kernel(const int2* __restrict__ sel, int* __restrict__ cnt,
                              int* __restrict__ idx, int2* __restrict__ pos) {
    __shared__ int local[NEXP];
    __shared__ int base[NEXP];
    const int tok = blockIdx.x * 256 + threadIdx.x;
    if (threadIdx.x < NEXP) local[threadIdx.x] = 0;
    __syncthreads();
    const int2 s = sel[tok];
    const int p0 = atomicAdd(&local[s.x], 1);
    const int p1 = atomicAdd(&local[s.y], 1);
    __syncthreads();
    if (threadIdx.x < NEXP) base[threadIdx.x] = atomicAdd(&cnt[threadIdx.x], local[threadIdx.x]);
    __syncthreads();
    const int g0 = base[s.x] + p0, g1 = base[s.y] + p1;
    idx[s.x * B_TOK + g0] = tok;
    idx[s.y * B_TOK + g1] = tok;
    pos[tok] = make_int2(g0, g1);
}

__global__ void padcnt_kernel(const int* __restrict__ cnt, int* __restrict__ padcnt) {
    const int e = threadIdx.x;
    if (e < NEXP) padcnt[e] = ((cnt[e] + 127) / 128) * 128;
}

__global__ void gather_sign_kernel(const float* __restrict__ x, const int* __restrict__ idx,
                                   const int* __restrict__ padcnt, uint8_t* __restrict__ xse) {
    const int e = blockIdx.y, p = blockIdx.x;
    if (p >= __ldg(&padcnt[e])) return;
    const int tok = idx[e * B_TOK + p];
    const float4* src = (const float4*)(x + (size_t)tok * IN_DIM);
    uint32_t* dst = (uint32_t*)(xse + ((size_t)e * B_TOK + p) * IN_DIM);
    for (int i = threadIdx.x; i < IN_DIM / 4; i += 128) {
        const float4 v = src[i];
        uint32_t b;
        b  = (v.x > 0.f ? S8_P1 : (v.x < 0.f ? S8_M1 : 0u));
        b |= (v.y > 0.f ? S8_P1 : (v.y < 0.f ? S8_M1 : 0u)) << 8;
        b |= (v.z > 0.f ? S8_P1 : (v.z < 0.f ? S8_M1 : 0u)) << 16;
        b |= (v.w > 0.f ? S8_P1 : (v.w < 0.f ? S8_M1 : 0u)) << 24;
        dst[i] = b;
    }
}

// ------------------------- final gate combine -------------------------
__global__ void combine_kernel(const __half* __restrict__ eo, const float2* __restrict__ gates,
                               const int2* __restrict__ sel, const int2* __restrict__ pos,
                               float* __restrict__ out) {
    const int b = blockIdx.x;
    const float2 g = gates[b];
    const int2 s = sel[b];
    const int2 p = pos[b];
    const __half2* e0 = (const __half2*)(eo + ((size_t)s.x * B_TOK + p.x) * NCLS_PAD);
    const __half2* e1 = (const __half2*)(eo + ((size_t)s.y * B_TOK + p.y) * NCLS_PAD);
    float2* o = (float2*)(out + (size_t)b * NCLS);
    for (int c = threadIdx.x; c < NCLS / 2; c += blockDim.x) {
        const float2 a = __half22float2(e0[c]);
        const float2 bb = __half22float2(e1[c]);
        float2 r;
        r.x = g.x * a.x + g.y * bb.x;
        r.y = g.x * a.y + g.y * bb.y;
        o[c] = r;
    }
}

// ------------------------- launcher -------------------------
extern "C" void kernel_launch(void* const* d_in, const int* in_sizes, int n_in,
                              void* d_out, int out_size) {
    const float* x   = (const float*)d_in[0];
    const float* Wr1 = (const float*)d_in[1];
    const float* br1 = (const float*)d_in[2];
    const float* Wr2 = (const float*)d_in[3];
    const float* br2 = (const float*)d_in[4];
    const float* Wr3 = (const float*)d_in[5];
    const float* br3 = (const float*)d_in[6];
    const float* W1  = (const float*)d_in[7];
    const float* g1  = (const float*)d_in[8];
    const float* b1  = (const float*)d_in[9];
    const float* W2  = (const float*)d_in[10];
    const float* g2  = (const float*)d_in[11];
    const float* b2  = (const float*)d_in[12];
    const float* W3  = (const float*)d_in[13];
    float* out = (float*)d_out;

    __half* h;           cudaGetSymbolAddress((void**)&h, d_h);
    uint8_t* s;          cudaGetSymbolAddress((void**)&s, d_s);
    uint8_t* w1t;        cudaGetSymbolAddress((void**)&w1t, d_w1t);
    uint8_t* w2t;        cudaGetSymbolAddress((void**)&w2t, d_w2t);
    uint8_t* w3t;        cudaGetSymbolAddress((void**)&w3t, d_w3t);
    uint8_t* xse;        cudaGetSymbolAddress((void**)&xse, d_xse);
    __nv_bfloat16* xsp;  cudaGetSymbolAddress((void**)&xsp, d_xsplit);
    __nv_bfloat16* wr1s; cudaGetSymbolAddress((void**)&wr1s, d_wr1s);
    __nv_bfloat16* wr2s; cudaGetSymbolAddress((void**)&wr2s, d_wr2s);
    __nv_bfloat16* r1s;  cudaGetSymbolAddress((void**)&r1s, d_r1s);
    float* r2;           cudaGetSymbolAddress((void**)&r2, d_r2);
    float2* gates;       cudaGetSymbolAddress((void**)&gates, d_gates);
    int2* sel;           cudaGetSymbolAddress((void**)&sel, d_sel);
    int2* pos;           cudaGetSymbolAddress((void**)&pos, d_pos);
    int* cnt;            cudaGetSymbolAddress((void**)&cnt, d_cnt);
    int* padcnt;         cudaGetSymbolAddress((void**)&padcnt, d_padcnt);
    int* idx;            cudaGetSymbolAddress((void**)&idx, d_idx);
    float* wpart;        cudaGetSymbolAddress((void**)&wpart, d_wpart);
    float* wmean;        cudaGetSymbolAddress((void**)&wmean, d_wmean);

    cudaFuncSetAttribute(gemm_s8_kernel,
                         cudaFuncAttributeMaxDynamicSharedMemorySize, S8_SMEM);

    // ---- weight ternarization -> s8 ----
    wsum_partial<<<dim3(256, NEXP), 256>>>(W1, wpart, (long)HID * IN_DIM / 4);
    wmean_final<<<NEXP, 256>>>(wpart, wmean + 0, (long)HID * IN_DIM, 256);
    ternarize_s8<<<dim3((HID * IN_DIM / 4 + 255) / 256, NEXP), 256>>>(W1, wmean + 0, w1t, HID, HID, IN_DIM);

    wsum_partial<<<dim3(256, NEXP), 256>>>(W2, wpart, (long)HID * HID / 4);
    wmean_final<<<NEXP, 256>>>(wpart, wmean + 4, (long)HID * HID, 256);
    ternarize_s8<<<dim3((HID * HID / 4 + 255) / 256, NEXP), 256>>>(W2, wmean + 4, w2t, HID, HID, HID);

    wsum_partial<<<dim3(256, NEXP), 256>>>(W3, wpart, (long)NCLS * HID / 4);
    wmean_final<<<NEXP, 256>>>(wpart, wmean + 8, (long)NCLS * HID, 256);
    ternarize_s8<<<dim3((NCLS_PAD * HID / 4 + 255) / 256, NEXP), 256>>>(W3, wmean + 8, w3t, NCLS, NCLS_PAD, HID);

    // ---- router prep + GEMMs (split-3 bf16; err ~1e-5) ----
    split3A_kernel<<<(B_TOK * IN_DIM) / 256, 256>>>(x, xsp, (long)B_TOK * IN_DIM);
    split3B_kernel<<<(RH * IN_DIM + 255) / 256, 256>>>(Wr1, wr1s, (long)RH * IN_DIM);
    split3B_kernel<<<(RH2 * RH + 255) / 256, 256>>>(Wr2, wr2s, (long)RH2 * RH);

    gemm_bf16_kernel<2><<<dim3(RH / 64, B_TOK / 128), 256>>>(
        xsp, wr1s, (void*)r1s, RH, IN_DIM * 3, br1);
    gemm_bf16_kernel<1><<<dim3(RH2 / 64, B_TOK / 128), 256>>>(
        r1s, wr2s, (void*)r2, RH2, RH * 3, br2);
    router_top2<<<B_TOK / 8, 256>>>(r2, Wr3, br3, gates, sel);

    // ---- top-2 compaction ----
    reset_cnt<<<1, 32>>>(cnt);
    assign_kernel<<<B_TOK / 256, 256>>>(sel, cnt, idx, pos);
    padcnt_kernel<<<1, 32>>>(cnt, padcnt);
    gather_sign_kernel<<<dim3(B_TOK, NEXP), 128>>>(x, idx, padcnt, xse);

    // ---- experts (exact ternary s8 IMMA, 128x256 tiles, fp16 out) ----
    gemm_s8_kernel<<<dim3(HID / 256, B_TOK / 128, NEXP), 256, S8_SMEM>>>(
        xse, (size_t)B_TOK * IN_DIM, w1t, (size_t)HID * IN_DIM, h,
        (size_t)B_TOK * HID, HID, IN_DIM, padcnt);
    ln_sign_kernel<<<dim3(B_TOK, NEXP), 256>>>(h, g1, b1, s, padcnt);

    gemm_s8_kernel<<<dim3(HID / 256, B_TOK / 128, NEXP), 256, S8_SMEM>>>(
        s, (size_t)B_TOK * HID, w2t, (size_t)HID * HID, h,
        (size_t)B_TOK * HID, HID, HID, padcnt);
    ln_sign_kernel<<<dim3(B_TOK, NEXP), 256>>>(h, g2, b2, s, padcnt);

    gemm_s8_kernel<<<dim3(NCLS_PAD / 256, B_TOK / 128, NEXP), 256, S8_SMEM>>>(
        s, (size_t)B_TOK * HID, w3t, (size_t)NCLS_PAD * HID, h,
        (size_t)B_TOK * NCLS_PAD, NCLS_PAD, HID, padcnt);

    // ---- top-2 gate combine ----
    combine_kernel<<<B_TOK, 256>>>(h, gates, sel, pos, out);
}

// round 12
// speedup vs baseline: 2.0098x; 2.0098x over previous
#include <cuda_runtime.h>
#include <cuda_bf16.h>
#include <cuda_fp16.h>
#include <cstdint>

#define B_TOK 8192
#define IN_DIM 512
#define HID 2048
#define NCLS 1000
#define NCLS_PAD 1024
#define NEXP 4
#define RH 256
#define RH2 128

#define FP8_P1 0x38u
#define FP8_M1 0xB8u

// ------------------------- scratch (device globals; no allocation) -------------------------
__device__ __half         d_h[(size_t)NEXP * B_TOK * HID];        // h1 / h2 / eo (fp16, exact ints)
__device__ uint8_t        d_s[(size_t)NEXP * B_TOK * HID];        // e4m3 sign activations {0,1}
__device__ uint8_t        d_w1t[(size_t)NEXP * HID * IN_DIM];     // e4m3 ternary weights
__device__ uint8_t        d_w2t[(size_t)NEXP * HID * HID];
__device__ uint8_t        d_w3t[(size_t)NEXP * NCLS_PAD * HID];
__device__ uint8_t        d_xse[(size_t)NEXP * B_TOK * IN_DIM];   // per-expert compacted sign(x)
__device__ __nv_bfloat16  d_xsplit[(size_t)B_TOK * IN_DIM * 3];   // split-3 x (router)
__device__ __nv_bfloat16  d_wr1s[(size_t)RH * IN_DIM * 3];
__device__ __nv_bfloat16  d_wr2s[(size_t)RH2 * RH * 3];
__device__ __nv_bfloat16  d_r1s[(size_t)B_TOK * RH * 3];          // split-3 relu(layer1)
__device__ float          d_r2[(size_t)B_TOK * RH2];
__device__ float2         d_gates[B_TOK];
__device__ int2           d_sel[B_TOK];
__device__ int2           d_pos[B_TOK];
__device__ int            d_cnt[NEXP];
__device__ int            d_padcnt[NEXP];
__device__ int            d_idx[NEXP * B_TOK];
__device__ float          d_wpart[NEXP * 256];
__device__ float          d_wmean[12];

// ------------------------- weight prep -------------------------

__global__ void wsum_partial(const float* __restrict__ W, float* __restrict__ part, long n4) {
    const int e = blockIdx.y;
    const float4* w = (const float4*)W + (size_t)e * n4;
    float s = 0.f;
    for (long i = (long)blockIdx.x * blockDim.x + threadIdx.x; i < n4;
         i += (long)gridDim.x * blockDim.x) {
        float4 v = w[i];
        s += (v.x + v.y) + (v.z + v.w);
    }
    __shared__ float sh[256];
    sh[threadIdx.x] = s;
    __syncthreads();
    for (int st = 128; st; st >>= 1) {
        if (threadIdx.x < st) sh[threadIdx.x] += sh[threadIdx.x + st];
        __syncthreads();
    }
    if (threadIdx.x == 0) part[e * gridDim.x + blockIdx.x] = sh[0];
}

__global__ void wmean_final(const float* __restrict__ part, float* __restrict__ mean,
                            long n, int nb) {
    const int e = blockIdx.x;
    __shared__ float sh[256];
    sh[threadIdx.x] = (threadIdx.x < nb) ? part[e * nb + threadIdx.x] : 0.f;
    __syncthreads();
    for (int st = 128; st; st >>= 1) {
        if (threadIdx.x < st) sh[threadIdx.x] += sh[threadIdx.x + st];
        __syncthreads();
    }
    if (threadIdx.x == 0) mean[e] = sh[0] / (float)n;
}

__global__ void ternarize_fp8(const float* __restrict__ W, const float* __restrict__ mean,
                              uint8_t* __restrict__ out, int in_rows, int out_rows, int cols) {
    const int e = blockIdx.y;
    const long n4 = (long)out_rows * cols / 4;
    long i = (long)blockIdx.x * blockDim.x + threadIdx.x;
    if (i >= n4) return;
    const long base = i * 4;
    const int r = (int)(base / cols), c = (int)(base % cols);
    uint32_t v = 0;
    if (r < in_rows) {
        const float m = mean[e];
        const float4 w = *(const float4*)(W + (size_t)e * in_rows * cols + (size_t)r * cols + c);
        const float d0 = w.x - m, d1 = w.y - m, d2 = w.z - m, d3 = w.w - m;
        v  = (d0 > 0.f ? FP8_P1 : (d0 < 0.f ? FP8_M1 : 0u));
        v |= (d1 > 0.f ? FP8_P1 : (d1 < 0.f ? FP8_M1 : 0u)) << 8;
        v |= (d2 > 0.f ? FP8_P1 : (d2 < 0.f ? FP8_M1 : 0u)) << 16;
        v |= (d3 > 0.f ? FP8_P1 : (d3 < 0.f ? FP8_M1 : 0u)) << 24;
    }
    *(uint32_t*)(out + (size_t)e * out_rows * cols + base) = v;
}

// ------------------------- split-3 fp32->bf16 (router; err ~2^-16) -------------------------

__device__ __forceinline__ void split3_store_A(__nv_bfloat16* o, float v) {
    __nv_bfloat16 h = __float2bfloat16(v);
    float r = v - __bfloat162float(h);
    __nv_bfloat16 m = __float2bfloat16(r);
    o[0] = h; o[1] = m; o[2] = h;
}

__global__ void split3A_kernel(const float* __restrict__ in, __nv_bfloat16* __restrict__ out, long n) {
    long i = (long)blockIdx.x * blockDim.x + threadIdx.x;
    if (i < n) split3_store_A(out + 3 * i, in[i]);
}

__global__ void split3B_kernel(const float* __restrict__ in, __nv_bfloat16* __restrict__ out, long n) {
    long i = (long)blockIdx.x * blockDim.x + threadIdx.x;
    if (i < n) {
        float v = in[i];
        __nv_bfloat16 h = __float2bfloat16(v);
        float r = v - __bfloat162float(h);
        __nv_bfloat16 m = __float2bfloat16(r);
        __nv_bfloat16* o = out + 3 * i;
        o[0] = h; o[1] = h; o[2] = m;
    }
}

// ------------------------- mma / ldmatrix / cp.async helpers -------------------------

__device__ __forceinline__ void mma_bf16(float* c, const uint32_t* a, const uint32_t* b) {
    asm volatile(
        "mma.sync.aligned.m16n8k16.row.col.f32.bf16.bf16.f32 "
        "{%0,%1,%2,%3}, {%4,%5,%6,%7}, {%8,%9}, {%0,%1,%2,%3};\n"
        : "+f"(c[0]), "+f"(c[1]), "+f"(c[2]), "+f"(c[3])
        : "r"(a[0]), "r"(a[1]), "r"(a[2]), "r"(a[3]), "r"(b[0]), "r"(b[1]));
}

// fp8 e4m3 MMA with fp16 accumulators (2x rate vs f32 accum on legacy pipe).
// Exact here: all partial sums are integers with |v| <= 2048 (fp16-exact range).
__device__ __forceinline__ void mma_fp8_f16(uint32_t* c, const uint32_t* a, const uint32_t* b) {
    asm volatile(
        "mma.sync.aligned.m16n8k32.row.col.f16.e4m3.e4m3.f16 "
        "{%0,%1}, {%2,%3,%4,%5}, {%6,%7}, {%0,%1};\n"
        : "+r"(c[0]), "+r"(c[1])
        : "r"(a[0]), "r"(a[1]), "r"(a[2]), "r"(a[3]), "r"(b[0]), "r"(b[1]));
}

__device__ __forceinline__ void ldsm4(uint32_t* r, uint32_t addr) {
    asm volatile("ldmatrix.sync.aligned.m8n8.x4.shared.b16 {%0,%1,%2,%3}, [%4];"
                 : "=r"(r[0]), "=r"(r[1]), "=r"(r[2]), "=r"(r[3]) : "r"(addr));
}

__device__ __forceinline__ void cp16(uint32_t smem, const void* gmem) {
    asm volatile("cp.async.cg.shared.global [%0], [%1], 16;\n" :: "r"(smem), "l"(gmem));
}
__device__ __forceinline__ void cp_commit() { asm volatile("cp.async.commit_group;\n"); }
template <int N>
__device__ __forceinline__ void cp_wait() {
    asm volatile("cp.async.wait_group %0;\n" :: "n"(N));
}

// ------------------------- FP8 tensor-core GEMM (experts; exact ternary) -------------------------
// C[M,N] = A[M,K] @ B[N,K]^T, e4m3 operands, f16 accum (exact ints <= 2048), fp16 store.
// Block 128x256x64, 4-stage cp.async, 8 warps (2x4), warp tile 64x64.
// smem 64B rows, swizzle chunk16 ^= (row>>1)&3 (conflict-free, XOR-linear in ks).

#define NSTG 4
#define ATB (128 * 64)
#define BTB (256 * 64)
#define STGB (ATB + BTB)
#define FP8_SMEM (NSTG * STGB)

__global__ void __launch_bounds__(256, 1) gemm_fp8_kernel(
    const uint8_t* __restrict__ A, size_t strideA,
    const uint8_t* __restrict__ Bm, size_t strideB,
    __half* __restrict__ C, size_t strideC,
    int N, int K, const int* __restrict__ mcnt)
{
    extern __shared__ uint8_t smdyn[];
    const int bm = blockIdx.y * 128;
    const int bn = blockIdx.x * 256;
    if (mcnt && bm >= __ldg(&mcnt[blockIdx.z])) return;
    A  += (size_t)blockIdx.z * strideA + (size_t)bm * K;
    Bm += (size_t)blockIdx.z * strideB + (size_t)bn * K;

    const uint32_t smb = (uint32_t)__cvta_generic_to_shared(smdyn);
    const int tid = threadIdx.x;
    const int lane = tid & 31, warp = tid >> 5;
    const int wm = (warp >> 2) * 64, wn = (warp & 3) * 64;
    const int t8 = lane >> 3, r8 = lane & 7;

    // ldsm base offsets (stage 0, ks 0)
    uint32_t aoff[4], boff[4];
#pragma unroll
    for (int mt = 0; mt < 4; mt++) {
        const int row = wm + mt * 16 + (t8 & 1) * 8 + r8;
        const int ch = (t8 >> 1) ^ ((row >> 1) & 3);
        aoff[mt] = smb + row * 64 + ch * 16;
    }
#pragma unroll
    for (int nt2 = 0; nt2 < 4; nt2++) {
        const int row = wn + nt2 * 16 + (t8 >> 1) * 8 + r8;
        const int ch = (t8 & 1) ^ ((row >> 1) & 3);
        boff[nt2] = smb + ATB + row * 64 + ch * 16;
    }

    // global->smem: 6 x 16B per thread per stage (A: 512 chunks, B: 1024 chunks)
    uint32_t dstoff[6];
    const uint8_t* gsrc[6];
#pragma unroll
    for (int i = 0; i < 6; i++) {
        int id = tid + 256 * i;
        if (id < 512) {
            const int row = id >> 2, ch = id & 3;
            dstoff[i] = smb + row * 64 + ((ch ^ ((row >> 1) & 3)) * 16);
            gsrc[i] = A + (size_t)row * K + ch * 16;
        } else {
            id -= 512;
            const int row = id >> 2, ch = id & 3;
            dstoff[i] = smb + ATB + row * 64 + ((ch ^ ((row >> 1) & 3)) * 16);
            gsrc[i] = Bm + (size_t)row * K + ch * 16;
        }
    }

    uint32_t acc[4][8][2];
#pragma unroll
    for (int mt = 0; mt < 4; mt++)
#pragma unroll
        for (int nt = 0; nt < 8; nt++) {
            acc[mt][nt][0] = 0u;
            acc[mt][nt][1] = 0u;
        }

    const int KC = K / 64;

#pragma unroll
    for (int p = 0; p < NSTG - 1; p++) {
        if (p < KC) {
            const uint32_t so = p * STGB;
#pragma unroll
            for (int i = 0; i < 6; i++) cp16(dstoff[i] + so, gsrc[i] + (size_t)p * 64);
        }
        cp_commit();
    }

    for (int c = 0; c < KC; c++) {
        cp_wait<NSTG - 2>();
        __syncthreads();

        const int pf = c + NSTG - 1;
        if (pf < KC) {
            const uint32_t so2 = (pf % NSTG) * STGB;
#pragma unroll
            for (int i = 0; i < 6; i++) cp16(dstoff[i] + so2, gsrc[i] + (size_t)pf * 64);
        }
        cp_commit();

        const uint32_t so = (c % NSTG) * STGB;
#pragma unroll
        for (int ks = 0; ks < 2; ks++) {
            uint32_t af[4][4];
            uint32_t bf[4][4];
#pragma unroll
            for (int mt = 0; mt < 4; mt++)
                ldsm4(af[mt], (aoff[mt] + so) ^ (ks << 5));
#pragma unroll
            for (int nt2 = 0; nt2 < 4; nt2++)
                ldsm4(bf[nt2], (boff[nt2] + so) ^ (ks << 5));
#pragma unroll
            for (int mt = 0; mt < 4; mt++)
#pragma unroll
                for (int nt = 0; nt < 8; nt++)
                    mma_fp8_f16(acc[mt][nt], af[mt], &bf[nt >> 1][(nt & 1) * 2]);
        }
    }

    // epilogue: accumulators are already packed half2 (exact integers)
    __half* Cz = C + (size_t)blockIdx.z * strideC;
#pragma unroll
    for (int mt = 0; mt < 4; mt++) {
#pragma unroll
        for (int nt = 0; nt < 8; nt++) {
            const int r0 = bm + wm + mt * 16 + (lane >> 2);
            const int cc = bn + wn + nt * 8 + (lane & 3) * 2;
            *(uint32_t*)(Cz + (size_t)r0 * N + cc)       = acc[mt][nt][0];
            *(uint32_t*)(Cz + (size_t)(r0 + 8) * N + cc) = acc[mt][nt][1];
        }
    }
}

// ------------------------- bf16 GEMM (router, split-3 exactness) -------------------------
// MODE 1: bias+relu fp32. MODE 2: bias+relu + split3A bf16 store.

template <int MODE>
__global__ void __launch_bounds__(256) gemm_bf16_kernel(
    const __nv_bfloat16* __restrict__ A,
    const __nv_bfloat16* __restrict__ Bm,
    void* __restrict__ Cv,
    int N, int K, const float* __restrict__ bias)
{
    const int bm = blockIdx.y * 128;
    const int bn = blockIdx.x * 64;
    A  += (size_t)bm * K;
    Bm += (size_t)bn * K;

    __shared__ __nv_bfloat16 As[2][128][40];
    __shared__ __nv_bfloat16 Bs[2][64][40];
    const uint32_t ASZ = 128 * 40 * 2, BSZ = 64 * 40 * 2;

    const int tid = threadIdx.x;
    const int lane = tid & 31, warp = tid >> 5;
    const int wm = (warp >> 1) * 32, wn = (warp & 1) * 32;
    const int t8 = lane >> 3, r8 = lane & 7;

    uint32_t aoff[2], boff[2];
#pragma unroll
    for (int mt = 0; mt < 2; mt++) {
        int row = wm + mt * 16 + (t8 & 1) * 8 + r8;
        int col = (t8 >> 1) * 8;
        aoff[mt] = (uint32_t)__cvta_generic_to_shared(&As[0][row][col]);
    }
#pragma unroll
    for (int nt2 = 0; nt2 < 2; nt2++) {
        int row = wn + nt2 * 16 + (t8 >> 1) * 8 + r8;
        int col = (t8 & 1) * 8;
        boff[nt2] = (uint32_t)__cvta_generic_to_shared(&Bs[0][row][col]);
    }

    const int arow = tid >> 2;
    const int acol = (tid & 3) * 8;
    const uint4* ag0 = (const uint4*)(A + (size_t)arow * K) + (tid & 3);
    const uint4* ag1 = (const uint4*)(A + (size_t)(arow + 64) * K) + (tid & 3);
    const uint4* bg  = (const uint4*)(Bm + (size_t)arow * K) + (tid & 3);

    float c[2][4][4];
#pragma unroll
    for (int mt = 0; mt < 2; mt++)
#pragma unroll
        for (int nt = 0; nt < 4; nt++)
#pragma unroll
            for (int j = 0; j < 4; j++) c[mt][nt][j] = 0.f;

    const int KT = K / 32;
    uint4 ra0 = ag0[0], ra1 = ag1[0], rb = bg[0];
    *(uint4*)&As[0][arow][acol]      = ra0;
    *(uint4*)&As[0][arow + 64][acol] = ra1;
    *(uint4*)&Bs[0][arow][acol]      = rb;
    __syncthreads();

    for (int kt = 0; kt < KT; kt++) {
        const int buf = kt & 1;
        if (kt + 1 < KT) {
            ra0 = ag0[(kt + 1) * 4];
            ra1 = ag1[(kt + 1) * 4];
            rb  = bg [(kt + 1) * 4];
        }
#pragma unroll
        for (int ks = 0; ks < 2; ks++) {
            uint32_t af[2][4];
            uint32_t bt[2][4];
#pragma unroll
            for (int mt = 0; mt < 2; mt++)
                ldsm4(af[mt], aoff[mt] + buf * ASZ + ks * 32);
#pragma unroll
            for (int nt2 = 0; nt2 < 2; nt2++)
                ldsm4(bt[nt2], boff[nt2] + buf * BSZ + ks * 32);
#pragma unroll
            for (int mt = 0; mt < 2; mt++)
#pragma unroll
                for (int nt = 0; nt < 4; nt++)
                    mma_bf16(c[mt][nt], af[mt], &bt[nt >> 1][(nt & 1) * 2]);
        }
        if (kt + 1 < KT) {
            *(uint4*)&As[buf ^ 1][arow][acol]      = ra0;
            *(uint4*)&As[buf ^ 1][arow + 64][acol] = ra1;
            *(uint4*)&Bs[buf ^ 1][arow][acol]      = rb;
        }
        __syncthreads();
    }

#pragma unroll
    for (int mt = 0; mt < 2; mt++) {
#pragma unroll
        for (int nt = 0; nt < 4; nt++) {
            const int r0 = bm + wm + mt * 16 + (lane >> 2);
            const int cc = bn + wn + nt * 8 + (lane & 3) * 2;
            const float v00 = c[mt][nt][0], v01 = c[mt][nt][1];
            const float v10 = c[mt][nt][2], v11 = c[mt][nt][3];
            const float b0 = bias[cc], b1 = bias[cc + 1];
            if (MODE == 1) {
                float* C = (float*)Cv;
                C[(size_t)r0 * N + cc]           = fmaxf(v00 + b0, 0.f);
                C[(size_t)r0 * N + cc + 1]       = fmaxf(v01 + b1, 0.f);
                C[(size_t)(r0 + 8) * N + cc]     = fmaxf(v10 + b0, 0.f);
                C[(size_t)(r0 + 8) * N + cc + 1] = fmaxf(v11 + b1, 0.f);
            } else {
                __nv_bfloat16* O = (__nv_bfloat16*)Cv;
                const size_t rs = (size_t)3 * N;
                split3_store_A(O + (size_t)r0 * rs + 3 * cc,       fmaxf(v00 + b0, 0.f));
                split3_store_A(O + (size_t)r0 * rs + 3 * (cc + 1), fmaxf(v01 + b1, 0.f));
                split3_store_A(O + (size_t)(r0 + 8) * rs + 3 * cc,       fmaxf(v10 + b0, 0.f));
                split3_store_A(O + (size_t)(r0 + 8) * rs + 3 * (cc + 1), fmaxf(v11 + b1, 0.f));
            }
        }
    }
}

// ------------------------- LayerNorm + ReLU + sign -> e4m3 {0,1} -------------------------
__global__ void ln_sign_kernel(const __half* __restrict__ h, const float* __restrict__ g,
                               const float* __restrict__ beta, uint8_t* __restrict__ out,
                               const int* __restrict__ padcnt) {
    const int bt = blockIdx.x;
    const int e = blockIdx.y;
    if (bt >= __ldg(&padcnt[e])) return;
    const size_t base = ((size_t)e * B_TOK + bt) * HID;
    const int tid = threadIdx.x;
    const int o0 = tid * 8;
    const uint4 raw = *(const uint4*)(h + base + o0);
    __half2 p[4];
    p[0] = *(const __half2*)&raw.x;
    p[1] = *(const __half2*)&raw.y;
    p[2] = *(const __half2*)&raw.z;
    p[3] = *(const __half2*)&raw.w;
    float v[8];
#pragma unroll
    for (int j = 0; j < 4; j++) {
        const float2 f = __half22float2(p[j]);
        v[2 * j] = f.x;
        v[2 * j + 1] = f.y;
    }
    float s = 0.f, q = 0.f;
#pragma unroll
    for (int j = 0; j < 8; j++) { s += v[j]; q += v[j] * v[j]; }
#pragma unroll
    for (int off = 16; off; off >>= 1) {
        s += __shfl_xor_sync(0xffffffffu, s, off);
        q += __shfl_xor_sync(0xffffffffu, q, off);
    }
    __shared__ float ss[8], qq[8];
    __shared__ float mu_s, rs_s;
    if ((tid & 31) == 0) { ss[tid >> 5] = s; qq[tid >> 5] = q; }
    __syncthreads();
    if (tid == 0) {
        float S = 0.f, Q = 0.f;
#pragma unroll
        for (int i = 0; i < 8; i++) { S += ss[i]; Q += qq[i]; }
        const float mu = S * (1.f / HID);
        const float var = Q * (1.f / HID) - mu * mu;
        mu_s = mu;
        rs_s = rsqrtf(var + 1e-5f);
    }
    __syncthreads();
    const float mu = mu_s, rs = rs_s;
    const float4 ga0 = *(const float4*)(g + (size_t)e * HID + o0);
    const float4 ga1 = *(const float4*)(g + (size_t)e * HID + o0 + 4);
    const float4 bb0 = *(const float4*)(beta + (size_t)e * HID + o0);
    const float4 bb1 = *(const float4*)(beta + (size_t)e * HID + o0 + 4);
    float y[8];
    y[0] = (v[0] - mu) * rs * ga0.x + bb0.x;
    y[1] = (v[1] - mu) * rs * ga0.y + bb0.y;
    y[2] = (v[2] - mu) * rs * ga0.z + bb0.z;
    y[3] = (v[3] - mu) * rs * ga0.w + bb0.w;
    y[4] = (v[4] - mu) * rs * ga1.x + bb1.x;
    y[5] = (v[5] - mu) * rs * ga1.y + bb1.y;
    y[6] = (v[6] - mu) * rs * ga1.z + bb1.z;
    y[7] = (v[7] - mu) * rs * ga1.w + bb1.w;
    uint32_t lo = 0, hi = 0;
#pragma unroll
    for (int j = 0; j < 4; j++) lo |= (y[j] > 0.f ? FP8_P1 : 0u) << (8 * j);
#pragma unroll
    for (int j = 0; j < 4; j++) hi |= (y[4 + j] > 0.f ? FP8_P1 : 0u) << (8 * j);
    *(uint2*)(out + base + o0) = make_uint2(lo, hi);
}

// ------------------------- router layer3 + softmax top-2 + gates -------------------------
__global__ void router_top2(const float* __restrict__ r2, const float* __restrict__ Wr3,
                            const float* __restrict__ br3, float2* __restrict__ gates,
                            int2* __restrict__ sel) {
    __shared__ float w[NEXP * RH2];
    __shared__ float bsh[NEXP];
    const int tid = threadIdx.x;
    for (int i = tid; i < NEXP * RH2; i += 256) w[i] = Wr3[i];
    if (tid < NEXP) bsh[tid] = br3[tid];
    __syncthreads();
    const int warp = tid >> 5, lane = tid & 31;
    const int token = blockIdx.x * 8 + warp;
    const float* xr = r2 + (size_t)token * RH2;
    float acc[NEXP] = {0.f, 0.f, 0.f, 0.f};
    for (int k = lane; k < RH2; k += 32) {
        const float xv = xr[k];
#pragma unroll
        for (int e = 0; e < NEXP; e++) acc[e] += xv * w[e * RH2 + k];
    }
#pragma unroll
    for (int e = 0; e < NEXP; e++)
#pragma unroll
        for (int off = 16; off; off >>= 1) acc[e] += __shfl_xor_sync(0xffffffffu, acc[e], off);
    if (lane == 0) {
        float sc[NEXP];
#pragma unroll
        for (int e = 0; e < NEXP; e++) sc[e] = acc[e] + bsh[e];
        int i0 = 0; float v0 = sc[0];
#pragma unroll
        for (int e = 1; e < NEXP; e++) if (sc[e] > v0) { v0 = sc[e]; i0 = e; }
        int i1 = -1; float v1 = -1e30f;
#pragma unroll
        for (int e = 0; e < NEXP; e++) if (e != i0 && sc[e] > v1) { v1 = sc[e]; i1 = e; }
        const float t = expf(v1 - v0);
        const float g0 = 1.f / (1.f + t);
        const float g1 = t / (1.f + t);
        gates[token] = make_float2(g0, g1);
        sel[token] = make_int2(i0, i1);
    }
}

// ------------------------- compaction -------------------------
__global__ void reset_cnt(int* __restrict__ cnt) {
    if (threadIdx.x < NEXP) cnt[threadIdx.x] = 0;
}

__global__ void assign_kernel(const int2* __restrict__ sel, int* __restrict__ cnt,
                              int* __restrict__ idx, int2* __restrict__ pos) {
    __shared__ int local[NEXP];
    __shared__ int base[NEXP];
    const int tok = blockIdx.x * 256 + threadIdx.x;
    if (threadIdx.x < NEXP) local[threadIdx.x] = 0;
    __syncthreads();
    const int2 s = sel[tok];
    const int p0 = atomicAdd(&local[s.x], 1);
    const int p1 = atomicAdd(&local[s.y], 1);
    __syncthreads();
    if (threadIdx.x < NEXP) base[threadIdx.x] = atomicAdd(&cnt[threadIdx.x], local[threadIdx.x]);
    __syncthreads();
    const int g0 = base[s.x] + p0, g1 = base[s.y] + p1;
    idx[s.x * B_TOK + g0] = tok;
    idx[s.y * B_TOK + g1] = tok;
    pos[tok] = make_int2(g0, g1);
}

__global__ void padcnt_kernel(const int* __restrict__ cnt, int* __restrict__ padcnt) {
    const int e = threadIdx.x;
    if (e < NEXP) padcnt[e] = ((cnt[e] + 127) / 128) * 128;
}

__global__ void gather_sign_kernel(const float* __restrict__ x, const int* __restrict__ idx,
                                   const int* __restrict__ padcnt, uint8_t* __restrict__ xse) {
    const int e = blockIdx.y, p = blockIdx.x;
    if (p >= __ldg(&padcnt[e])) return;
    const int tok = idx[e * B_TOK + p];
    const float4* src = (const float4*)(x + (size_t)tok * IN_DIM);
    uint32_t* dst = (uint32_t*)(xse + ((size_t)e * B_TOK + p) * IN_DIM);
    for (int i = threadIdx.x; i < IN_DIM / 4; i += 128) {
        const float4 v = src[i];
        uint32_t b;
        b  = (v.x > 0.f ? FP8_P1 : (v.x < 0.f ? FP8_M1 : 0u));
        b |= (v.y > 0.f ? FP8_P1 : (v.y < 0.f ? FP8_M1 : 0u)) << 8;
        b |= (v.z > 0.f ? FP8_P1 : (v.z < 0.f ? FP8_M1 : 0u)) << 16;
        b |= (v.w > 0.f ? FP8_P1 : (v.w < 0.f ? FP8_M1 : 0u)) << 24;
        dst[i] = b;
    }
}

// ------------------------- final gate combine -------------------------
__global__ void combine_kernel(const __half* __restrict__ eo, const float2* __restrict__ gates,
                               const int2* __restrict__ sel, const int2* __restrict__ pos,
                               float* __restrict__ out) {
    const int b = blockIdx.x;
    const float2 g = gates[b];
    const int2 s = sel[b];
    const int2 p = pos[b];
    const __half2* e0 = (const __half2*)(eo + ((size_t)s.x * B_TOK + p.x) * NCLS_PAD);
    const __half2* e1 = (const __half2*)(eo + ((size_t)s.y * B_TOK + p.y) * NCLS_PAD);
    float2* o = (float2*)(out + (size_t)b * NCLS);
    for (int c = threadIdx.x; c < NCLS / 2; c += blockDim.x) {
        const float2 a = __half22float2(e0[c]);
        const float2 bb = __half22float2(e1[c]);
        float2 r;
        r.x = g.x * a.x + g.y * bb.x;
        r.y = g.x * a.y + g.y * bb.y;
        o[c] = r;
    }
}

// ------------------------- launcher -------------------------
extern "C" void kernel_launch(void* const* d_in, const int* in_sizes, int n_in,
                              void* d_out, int out_size) {
    const float* x   = (const float*)d_in[0];
    const float* Wr1 = (const float*)d_in[1];
    const float* br1 = (const float*)d_in[2];
    const float* Wr2 = (const float*)d_in[3];
    const float* br2 = (const float*)d_in[4];
    const float* Wr3 = (const float*)d_in[5];
    const float* br3 = (const float*)d_in[6];
    const float* W1  = (const float*)d_in[7];
    const float* g1  = (const float*)d_in[8];
    const float* b1  = (const float*)d_in[9];
    const float* W2  = (const float*)d_in[10];
    const float* g2  = (const float*)d_in[11];
    const float* b2  = (const float*)d_in[12];
    const float* W3  = (const float*)d_in[13];
    float* out = (float*)d_out;

    __half* h;           cudaGetSymbolAddress((void**)&h, d_h);
    uint8_t* s;          cudaGetSymbolAddress((void**)&s, d_s);
    uint8_t* w1t;        cudaGetSymbolAddress((void**)&w1t, d_w1t);
    uint8_t* w2t;        cudaGetSymbolAddress((void**)&w2t, d_w2t);
    uint8_t* w3t;        cudaGetSymbolAddress((void**)&w3t, d_w3t);
    uint8_t* xse;        cudaGetSymbolAddress((void**)&xse, d_xse);
    __nv_bfloat16* xsp;  cudaGetSymbolAddress((void**)&xsp, d_xsplit);
    __nv_bfloat16* wr1s; cudaGetSymbolAddress((void**)&wr1s, d_wr1s);
    __nv_bfloat16* wr2s; cudaGetSymbolAddress((void**)&wr2s, d_wr2s);
    __nv_bfloat16* r1s;  cudaGetSymbolAddress((void**)&r1s, d_r1s);
    float* r2;           cudaGetSymbolAddress((void**)&r2, d_r2);
    float2* gates;       cudaGetSymbolAddress((void**)&gates, d_gates);
    int2* sel;           cudaGetSymbolAddress((void**)&sel, d_sel);
    int2* pos;           cudaGetSymbolAddress((void**)&pos, d_pos);
    int* cnt;            cudaGetSymbolAddress((void**)&cnt, d_cnt);
    int* padcnt;         cudaGetSymbolAddress((void**)&padcnt, d_padcnt);
    int* idx;            cudaGetSymbolAddress((void**)&idx, d_idx);
    float* wpart;        cudaGetSymbolAddress((void**)&wpart, d_wpart);
    float* wmean;        cudaGetSymbolAddress((void**)&wmean, d_wmean);

    cudaFuncSetAttribute(gemm_fp8_kernel,
                         cudaFuncAttributeMaxDynamicSharedMemorySize, FP8_SMEM);

    // ---- weight ternarization -> e4m3 ----
    wsum_partial<<<dim3(256, NEXP), 256>>>(W1, wpart, (long)HID * IN_DIM / 4);
    wmean_final<<<NEXP, 256>>>(wpart, wmean + 0, (long)HID * IN_DIM, 256);
    ternarize_fp8<<<dim3((HID * IN_DIM / 4 + 255) / 256, NEXP), 256>>>(W1, wmean + 0, w1t, HID, HID, IN_DIM);

    wsum_partial<<<dim3(256, NEXP), 256>>>(W2, wpart, (long)HID * HID / 4);
    wmean_final<<<NEXP, 256>>>(wpart, wmean + 4, (long)HID * HID, 256);
    ternarize_fp8<<<dim3((HID * HID / 4 + 255) / 256, NEXP), 256>>>(W2, wmean + 4, w2t, HID, HID, HID);

    wsum_partial<<<dim3(256, NEXP), 256>>>(W3, wpart, (long)NCLS * HID / 4);
    wmean_final<<<NEXP, 256>>>(wpart, wmean + 8, (long)NCLS * HID, 256);
    ternarize_fp8<<<dim3((NCLS_PAD * HID / 4 + 255) / 256, NEXP), 256>>>(W3, wmean + 8, w3t, NCLS, NCLS_PAD, HID);

    // ---- router prep + GEMMs (split-3 bf16; err ~1e-5) ----
    split3A_kernel<<<(B_TOK * IN_DIM) / 256, 256>>>(x, xsp, (long)B_TOK * IN_DIM);
    split3B_kernel<<<(RH * IN_DIM + 255) / 256, 256>>>(Wr1, wr1s, (long)RH * IN_DIM);
    split3B_kernel<<<(RH2 * RH + 255) / 256, 256>>>(Wr2, wr2s, (long)RH2 * RH);

    gemm_bf16_kernel<2><<<dim3(RH / 64, B_TOK / 128), 256>>>(
        xsp, wr1s, (void*)r1s, RH, IN_DIM * 3, br1);
    gemm_bf16_kernel<1><<<dim3(RH2 / 64, B_TOK / 128), 256>>>(
        r1s, wr2s, (void*)r2, RH2, RH * 3, br2);
    router_top2<<<B_TOK / 8, 256>>>(r2, Wr3, br3, gates, sel);

    // ---- top-2 compaction ----
    reset_cnt<<<1, 32>>>(cnt);
    assign_kernel<<<B_TOK / 256, 256>>>(sel, cnt, idx, pos);
    padcnt_kernel<<<1, 32>>>(cnt, padcnt);
    gather_sign_kernel<<<dim3(B_TOK, NEXP), 128>>>(x, idx, padcnt, xse);

    // ---- experts (exact ternary e4m3 MMA, f16 accum, 128x256 tiles) ----
    gemm_fp8_kernel<<<dim3(HID / 256, B_TOK / 128, NEXP), 256, FP8_SMEM>>>(
        xse, (size_t)B_TOK * IN_DIM, w1t, (size_t)HID * IN_DIM, h,
        (size_t)B_TOK * HID, HID, IN_DIM, padcnt);
    ln_sign_kernel<<<dim3(B_TOK, NEXP), 256>>>(h, g1, b1, s, padcnt);

    gemm_fp8_kernel<<<dim3(HID / 256, B_TOK / 128, NEXP), 256, FP8_SMEM>>>(
        s, (size_t)B_TOK * HID, w2t, (size_t)HID * HID, h,
        (size_t)B_TOK * HID, HID, HID, padcnt);
    ln_sign_kernel<<<dim3(B_TOK, NEXP), 256>>>(h, g2, b2, s, padcnt);

    gemm_fp8_kernel<<<dim3(NCLS_PAD / 256, B_TOK / 128, NEXP), 256, FP8_SMEM>>>(
        s, (size_t)B_TOK * HID, w3t, (size_t)NCLS_PAD * HID, h,
        (size_t)B_TOK * NCLS_PAD, NCLS_PAD, HID, padcnt);

    // ---- top-2 gate combine ----
    combine_kernel<<<B_TOK, 256>>>(h, gates, sel, pos, out);
}

// round 13
// speedup vs baseline: 2.0714x; 1.0306x over previous
#include <cuda_runtime.h>
#include <cuda_bf16.h>
#include <cuda_fp16.h>
#include <cstdint>

#define B_TOK 8192
#define IN_DIM 512
#define HID 2048
#define NCLS 1000
#define NCLS_PAD 1024
#define NEXP 4
#define RH 256
#define RH2 128

#define FP8_P1 0x38u
#define FP8_M1 0xB8u

// ------------------------- scratch (device globals; no allocation) -------------------------
__device__ __half         d_h[(size_t)NEXP * B_TOK * HID];        // h1 / h2 / eo (fp16, exact ints)
__device__ uint8_t        d_s[(size_t)NEXP * B_TOK * HID];        // e4m3 sign activations {0,1}
__device__ uint8_t        d_w1t[(size_t)NEXP * HID * IN_DIM];     // e4m3 ternary weights
__device__ uint8_t        d_w2t[(size_t)NEXP * HID * HID];
__device__ uint8_t        d_w3t[(size_t)NEXP * NCLS_PAD * HID];
__device__ uint8_t        d_xse[(size_t)NEXP * B_TOK * IN_DIM];   // per-expert compacted sign(x)
__device__ __nv_bfloat16  d_xsplit[(size_t)B_TOK * IN_DIM * 3];   // split-3 x (router)
__device__ __nv_bfloat16  d_wr1s[(size_t)RH * IN_DIM * 3];
__device__ __nv_bfloat16  d_wr2s[(size_t)RH2 * RH * 3];
__device__ __nv_bfloat16  d_r1s[(size_t)B_TOK * RH * 3];          // split-3 relu(layer1)
__device__ float          d_r2[(size_t)B_TOK * RH2];
__device__ float2         d_gates[B_TOK];
__device__ int2           d_sel[B_TOK];
__device__ int2           d_pos[B_TOK];
__device__ int            d_cnt[NEXP];
__device__ int            d_padcnt[NEXP];
__device__ int            d_idx[NEXP * B_TOK];
__device__ float          d_wpart[NEXP * 256];
__device__ float          d_wmean[12];

// ------------------------- weight prep -------------------------

__global__ void wsum_partial(const float* __restrict__ W, float* __restrict__ part, long n4) {
    const int e = blockIdx.y;
    const float4* w = (const float4*)W + (size_t)e * n4;
    float s = 0.f;
    for (long i = (long)blockIdx.x * blockDim.x + threadIdx.x; i < n4;
         i += (long)gridDim.x * blockDim.x) {
        float4 v = w[i];
        s += (v.x + v.y) + (v.z + v.w);
    }
    __shared__ float sh[256];
    sh[threadIdx.x] = s;
    __syncthreads();
    for (int st = 128; st; st >>= 1) {
        if (threadIdx.x < st) sh[threadIdx.x] += sh[threadIdx.x + st];
        __syncthreads();
    }
    if (threadIdx.x == 0) part[e * gridDim.x + blockIdx.x] = sh[0];
}

__global__ void wmean_final(const float* __restrict__ part, float* __restrict__ mean,
                            long n, int nb) {
    const int e = blockIdx.x;
    __shared__ float sh[256];
    sh[threadIdx.x] = (threadIdx.x < nb) ? part[e * nb + threadIdx.x] : 0.f;
    __syncthreads();
    for (int st = 128; st; st >>= 1) {
        if (threadIdx.x < st) sh[threadIdx.x] += sh[threadIdx.x + st];
        __syncthreads();
    }
    if (threadIdx.x == 0) mean[e] = sh[0] / (float)n;
}

__global__ void ternarize_fp8(const float* __restrict__ W, const float* __restrict__ mean,
                              uint8_t* __restrict__ out, int in_rows, int out_rows, int cols) {
    const int e = blockIdx.y;
    const long n4 = (long)out_rows * cols / 4;
    long i = (long)blockIdx.x * blockDim.x + threadIdx.x;
    if (i >= n4) return;
    const long base = i * 4;
    const int r = (int)(base / cols), c = (int)(base % cols);
    uint32_t v = 0;
    if (r < in_rows) {
        const float m = mean[e];
        const float4 w = *(const float4*)(W + (size_t)e * in_rows * cols + (size_t)r * cols + c);
        const float d0 = w.x - m, d1 = w.y - m, d2 = w.z - m, d3 = w.w - m;
        v  = (d0 > 0.f ? FP8_P1 : (d0 < 0.f ? FP8_M1 : 0u));
        v |= (d1 > 0.f ? FP8_P1 : (d1 < 0.f ? FP8_M1 : 0u)) << 8;
        v |= (d2 > 0.f ? FP8_P1 : (d2 < 0.f ? FP8_M1 : 0u)) << 16;
        v |= (d3 > 0.f ? FP8_P1 : (d3 < 0.f ? FP8_M1 : 0u)) << 24;
    }
    *(uint32_t*)(out + (size_t)e * out_rows * cols + base) = v;
}

// ------------------------- split-3 fp32->bf16 (router; err ~2^-16) -------------------------

__device__ __forceinline__ void split3_store_A(__nv_bfloat16* o, float v) {
    __nv_bfloat16 h = __float2bfloat16(v);
    float r = v - __bfloat162float(h);
    __nv_bfloat16 m = __float2bfloat16(r);
    o[0] = h; o[1] = m; o[2] = h;
}

__global__ void split3A_kernel(const float* __restrict__ in, __nv_bfloat16* __restrict__ out, long n) {
    long i = (long)blockIdx.x * blockDim.x + threadIdx.x;
    if (i < n) split3_store_A(out + 3 * i, in[i]);
}

__global__ void split3B_kernel(const float* __restrict__ in, __nv_bfloat16* __restrict__ out, long n) {
    long i = (long)blockIdx.x * blockDim.x + threadIdx.x;
    if (i < n) {
        float v = in[i];
        __nv_bfloat16 h = __float2bfloat16(v);
        float r = v - __bfloat162float(h);
        __nv_bfloat16 m = __float2bfloat16(r);
        __nv_bfloat16* o = out + 3 * i;
        o[0] = h; o[1] = h; o[2] = m;
    }
}

// ------------------------- mma / ldmatrix / cp.async helpers -------------------------

__device__ __forceinline__ void mma_bf16(float* c, const uint32_t* a, const uint32_t* b) {
    asm volatile(
        "mma.sync.aligned.m16n8k16.row.col.f32.bf16.bf16.f32 "
        "{%0,%1,%2,%3}, {%4,%5,%6,%7}, {%8,%9}, {%0,%1,%2,%3};\n"
        : "+f"(c[0]), "+f"(c[1]), "+f"(c[2]), "+f"(c[3])
        : "r"(a[0]), "r"(a[1]), "r"(a[2]), "r"(a[3]), "r"(b[0]), "r"(b[1]));
}

// fp8 e4m3 MMA with fp16 accumulators; exact here (integers, |v| <= 2048)
__device__ __forceinline__ void mma_fp8_f16(uint32_t* c, const uint32_t* a, const uint32_t* b) {
    asm volatile(
        "mma.sync.aligned.m16n8k32.row.col.f16.e4m3.e4m3.f16 "
        "{%0,%1}, {%2,%3,%4,%5}, {%6,%7}, {%0,%1};\n"
        : "+r"(c[0]), "+r"(c[1])
        : "r"(a[0]), "r"(a[1]), "r"(a[2]), "r"(a[3]), "r"(b[0]), "r"(b[1]));
}

__device__ __forceinline__ void ldsm4(uint32_t* r, uint32_t addr) {
    asm volatile("ldmatrix.sync.aligned.m8n8.x4.shared.b16 {%0,%1,%2,%3}, [%4];"
                 : "=r"(r[0]), "=r"(r[1]), "=r"(r[2]), "=r"(r[3]) : "r"(addr));
}

__device__ __forceinline__ void cp16(uint32_t smem, const void* gmem) {
    asm volatile("cp.async.cg.shared.global [%0], [%1], 16;\n" :: "r"(smem), "l"(gmem));
}
__device__ __forceinline__ void cp_commit() { asm volatile("cp.async.commit_group;\n"); }
template <int N>
__device__ __forceinline__ void cp_wait() {
    asm volatile("cp.async.wait_group %0;\n" :: "n"(N));
}

// ------------------------- FP8 tensor-core GEMM (experts; exact ternary) -------------------------
// C[M,N] = A[M,K] @ B[N,K]^T, e4m3 operands, f16 accum (exact), fp16 store.
// Block 256x256x64, 512 threads (16 warps, 4x4), warp tile 64x64 (unchanged inner loop).
// 4-stage cp.async; smem 64B rows, swizzle chunk16 ^= (row>>1)&3.

#define NSTG 4
#define ATB (256 * 64)
#define BTB (256 * 64)
#define STGB (ATB + BTB)
#define FP8_SMEM (NSTG * STGB)

__global__ void __launch_bounds__(512, 1) gemm_fp8_kernel(
    const uint8_t* __restrict__ A, size_t strideA,
    const uint8_t* __restrict__ Bm, size_t strideB,
    __half* __restrict__ C, size_t strideC,
    int N, int K, const int* __restrict__ mcnt)
{
    extern __shared__ uint8_t smdyn[];
    const int bm = blockIdx.y * 256;
    const int bn = blockIdx.x * 256;
    if (mcnt && bm >= __ldg(&mcnt[blockIdx.z])) return;
    A  += (size_t)blockIdx.z * strideA + (size_t)bm * K;
    Bm += (size_t)blockIdx.z * strideB + (size_t)bn * K;

    const uint32_t smb = (uint32_t)__cvta_generic_to_shared(smdyn);
    const int tid = threadIdx.x;
    const int lane = tid & 31, warp = tid >> 5;
    const int wm = (warp >> 2) * 64, wn = (warp & 3) * 64;
    const int t8 = lane >> 3, r8 = lane & 7;

    // ldsm base offsets (stage 0, ks 0)
    uint32_t aoff[4], boff[4];
#pragma unroll
    for (int mt = 0; mt < 4; mt++) {
        const int row = wm + mt * 16 + (t8 & 1) * 8 + r8;
        const int ch = (t8 >> 1) ^ ((row >> 1) & 3);
        aoff[mt] = smb + row * 64 + ch * 16;
    }
#pragma unroll
    for (int nt2 = 0; nt2 < 4; nt2++) {
        const int row = wn + nt2 * 16 + (t8 >> 1) * 8 + r8;
        const int ch = (t8 & 1) ^ ((row >> 1) & 3);
        boff[nt2] = smb + ATB + row * 64 + ch * 16;
    }

    // global->smem: 4 x 16B per thread per stage
    // rows: grow and grow+128 for both A and B ((row+128) keeps same swizzle: 128>>1 ≡ 0 mod 4)
    const int grow = tid >> 2;               // 0..127
    const int gch = tid & 3;
    const uint32_t dstA = smb + grow * 64 + ((gch ^ ((grow >> 1) & 3)) * 16);
    const uint32_t dstB = dstA + ATB;
    const uint8_t* agp = A + (size_t)grow * K + gch * 16;
    const uint8_t* bgp = Bm + (size_t)grow * K + gch * 16;
    const size_t rs128 = (size_t)128 * K;

    uint32_t acc[4][8][2];
#pragma unroll
    for (int mt = 0; mt < 4; mt++)
#pragma unroll
        for (int nt = 0; nt < 8; nt++) {
            acc[mt][nt][0] = 0u;
            acc[mt][nt][1] = 0u;
        }

    const int KC = K / 64;

#pragma unroll
    for (int p = 0; p < NSTG - 1; p++) {
        if (p < KC) {
            const uint32_t so = p * STGB;
            cp16(dstA + so, agp + (size_t)p * 64);
            cp16(dstA + so + 128 * 64, agp + (size_t)p * 64 + rs128);
            cp16(dstB + so, bgp + (size_t)p * 64);
            cp16(dstB + so + 128 * 64, bgp + (size_t)p * 64 + rs128);
        }
        cp_commit();
    }

    for (int c = 0; c < KC; c++) {
        cp_wait<NSTG - 2>();
        __syncthreads();

        const int pf = c + NSTG - 1;
        if (pf < KC) {
            const uint32_t so2 = (pf % NSTG) * STGB;
            cp16(dstA + so2, agp + (size_t)pf * 64);
            cp16(dstA + so2 + 128 * 64, agp + (size_t)pf * 64 + rs128);
            cp16(dstB + so2, bgp + (size_t)pf * 64);
            cp16(dstB + so2 + 128 * 64, bgp + (size_t)pf * 64 + rs128);
        }
        cp_commit();

        const uint32_t so = (c % NSTG) * STGB;
#pragma unroll
        for (int ks = 0; ks < 2; ks++) {
            uint32_t af[4][4];
            uint32_t bf[4][4];
#pragma unroll
            for (int mt = 0; mt < 4; mt++)
                ldsm4(af[mt], (aoff[mt] + so) ^ (ks << 5));
#pragma unroll
            for (int nt2 = 0; nt2 < 4; nt2++)
                ldsm4(bf[nt2], (boff[nt2] + so) ^ (ks << 5));
#pragma unroll
            for (int mt = 0; mt < 4; mt++)
#pragma unroll
                for (int nt = 0; nt < 8; nt++)
                    mma_fp8_f16(acc[mt][nt], af[mt], &bf[nt >> 1][(nt & 1) * 2]);
        }
    }

    // epilogue: accumulators are packed half2 (exact integers)
    __half* Cz = C + (size_t)blockIdx.z * strideC;
#pragma unroll
    for (int mt = 0; mt < 4; mt++) {
#pragma unroll
        for (int nt = 0; nt < 8; nt++) {
            const int r0 = bm + wm + mt * 16 + (lane >> 2);
            const int cc = bn + wn + nt * 8 + (lane & 3) * 2;
            *(uint32_t*)(Cz + (size_t)r0 * N + cc)       = acc[mt][nt][0];
            *(uint32_t*)(Cz + (size_t)(r0 + 8) * N + cc) = acc[mt][nt][1];
        }
    }
}

// ------------------------- bf16 GEMM (router, split-3 exactness) -------------------------
// MODE 1: bias+relu fp32. MODE 2: bias+relu + split3A bf16 store.

template <int MODE>
__global__ void __launch_bounds__(256) gemm_bf16_kernel(
    const __nv_bfloat16* __restrict__ A,
    const __nv_bfloat16* __restrict__ Bm,
    void* __restrict__ Cv,
    int N, int K, const float* __restrict__ bias)
{
    const int bm = blockIdx.y * 128;
    const int bn = blockIdx.x * 64;
    A  += (size_t)bm * K;
    Bm += (size_t)bn * K;

    __shared__ __nv_bfloat16 As[2][128][40];
    __shared__ __nv_bfloat16 Bs[2][64][40];
    const uint32_t ASZ = 128 * 40 * 2, BSZ = 64 * 40 * 2;

    const int tid = threadIdx.x;
    const int lane = tid & 31, warp = tid >> 5;
    const int wm = (warp >> 1) * 32, wn = (warp & 1) * 32;
    const int t8 = lane >> 3, r8 = lane & 7;

    uint32_t aoff[2], boff[2];
#pragma unroll
    for (int mt = 0; mt < 2; mt++) {
        int row = wm + mt * 16 + (t8 & 1) * 8 + r8;
        int col = (t8 >> 1) * 8;
        aoff[mt] = (uint32_t)__cvta_generic_to_shared(&As[0][row][col]);
    }
#pragma unroll
    for (int nt2 = 0; nt2 < 2; nt2++) {
        int row = wn + nt2 * 16 + (t8 >> 1) * 8 + r8;
        int col = (t8 & 1) * 8;
        boff[nt2] = (uint32_t)__cvta_generic_to_shared(&Bs[0][row][col]);
    }

    const int arow = tid >> 2;
    const int acol = (tid & 3) * 8;
    const uint4* ag0 = (const uint4*)(A + (size_t)arow * K) + (tid & 3);
    const uint4* ag1 = (const uint4*)(A + (size_t)(arow + 64) * K) + (tid & 3);
    const uint4* bg  = (const uint4*)(Bm + (size_t)arow * K) + (tid & 3);

    float c[2][4][4];
#pragma unroll
    for (int mt = 0; mt < 2; mt++)
#pragma unroll
        for (int nt = 0; nt < 4; nt++)
#pragma unroll
            for (int j = 0; j < 4; j++) c[mt][nt][j] = 0.f;

    const int KT = K / 32;
    uint4 ra0 = ag0[0], ra1 = ag1[0], rb = bg[0];
    *(uint4*)&As[0][arow][acol]      = ra0;
    *(uint4*)&As[0][arow + 64][acol] = ra1;
    *(uint4*)&Bs[0][arow][acol]      = rb;
    __syncthreads();

    for (int kt = 0; kt < KT; kt++) {
        const int buf = kt & 1;
        if (kt + 1 < KT) {
            ra0 = ag0[(kt + 1) * 4];
            ra1 = ag1[(kt + 1) * 4];
            rb  = bg [(kt + 1) * 4];
        }
#pragma unroll
        for (int ks = 0; ks < 2; ks++) {
            uint32_t af[2][4];
            uint32_t bt[2][4];
#pragma unroll
            for (int mt = 0; mt < 2; mt++)
                ldsm4(af[mt], aoff[mt] + buf * ASZ + ks * 32);
#pragma unroll
            for (int nt2 = 0; nt2 < 2; nt2++)
                ldsm4(bt[nt2], boff[nt2] + buf * BSZ + ks * 32);
#pragma unroll
            for (int mt = 0; mt < 2; mt++)
#pragma unroll
                for (int nt = 0; nt < 4; nt++)
                    mma_bf16(c[mt][nt], af[mt], &bt[nt >> 1][(nt & 1) * 2]);
        }
        if (kt + 1 < KT) {
            *(uint4*)&As[buf ^ 1][arow][acol]      = ra0;
            *(uint4*)&As[buf ^ 1][arow + 64][acol] = ra1;
            *(uint4*)&Bs[buf ^ 1][arow][acol]      = rb;
        }
        __syncthreads();
    }

#pragma unroll
    for (int mt = 0; mt < 2; mt++) {
#pragma unroll
        for (int nt = 0; nt < 4; nt++) {
            const int r0 = bm + wm + mt * 16 + (lane >> 2);
            const int cc = bn + wn + nt * 8 + (lane & 3) * 2;
            const float v00 = c[mt][nt][0], v01 = c[mt][nt][1];
            const float v10 = c[mt][nt][2], v11 = c[mt][nt][3];
            const float b0 = bias[cc], b1 = bias[cc + 1];
            if (MODE == 1) {
                float* C = (float*)Cv;
                C[(size_t)r0 * N + cc]           = fmaxf(v00 + b0, 0.f);
                C[(size_t)r0 * N + cc + 1]       = fmaxf(v01 + b1, 0.f);
                C[(size_t)(r0 + 8) * N + cc]     = fmaxf(v10 + b0, 0.f);
                C[(size_t)(r0 + 8) * N + cc + 1] = fmaxf(v11 + b1, 0.f);
            } else {
                __nv_bfloat16* O = (__nv_bfloat16*)Cv;
                const size_t rs = (size_t)3 * N;
                split3_store_A(O + (size_t)r0 * rs + 3 * cc,       fmaxf(v00 + b0, 0.f));
                split3_store_A(O + (size_t)r0 * rs + 3 * (cc + 1), fmaxf(v01 + b1, 0.f));
                split3_store_A(O + (size_t)(r0 + 8) * rs + 3 * cc,       fmaxf(v10 + b0, 0.f));
                split3_store_A(O + (size_t)(r0 + 8) * rs + 3 * (cc + 1), fmaxf(v11 + b1, 0.f));
            }
        }
    }
}

// ------------------------- LayerNorm + ReLU + sign -> e4m3 {0,1} -------------------------
__global__ void ln_sign_kernel(const __half* __restrict__ h, const float* __restrict__ g,
                               const float* __restrict__ beta, uint8_t* __restrict__ out,
                               const int* __restrict__ padcnt) {
    const int bt = blockIdx.x;
    const int e = blockIdx.y;
    if (bt >= __ldg(&padcnt[e])) return;
    const size_t base = ((size_t)e * B_TOK + bt) * HID;
    const int tid = threadIdx.x;
    const int o0 = tid * 8;
    const uint4 raw = *(const uint4*)(h + base + o0);
    __half2 p[4];
    p[0] = *(const __half2*)&raw.x;
    p[1] = *(const __half2*)&raw.y;
    p[2] = *(const __half2*)&raw.z;
    p[3] = *(const __half2*)&raw.w;
    float v[8];
#pragma unroll
    for (int j = 0; j < 4; j++) {
        const float2 f = __half22float2(p[j]);
        v[2 * j] = f.x;
        v[2 * j + 1] = f.y;
    }
    float s = 0.f, q = 0.f;
#pragma unroll
    for (int j = 0; j < 8; j++) { s += v[j]; q += v[j] * v[j]; }
#pragma unroll
    for (int off = 16; off; off >>= 1) {
        s += __shfl_xor_sync(0xffffffffu, s, off);
        q += __shfl_xor_sync(0xffffffffu, q, off);
    }
    __shared__ float ss[8], qq[8];
    __shared__ float mu_s, rs_s;
    if ((tid & 31) == 0) { ss[tid >> 5] = s; qq[tid >> 5] = q; }
    __syncthreads();
    if (tid == 0) {
        float S = 0.f, Q = 0.f;
#pragma unroll
        for (int i = 0; i < 8; i++) { S += ss[i]; Q += qq[i]; }
        const float mu = S * (1.f / HID);
        const float var = Q * (1.f / HID) - mu * mu;
        mu_s = mu;
        rs_s = rsqrtf(var + 1e-5f);
    }
    __syncthreads();
    const float mu = mu_s, rs = rs_s;
    const float4 ga0 = *(const float4*)(g + (size_t)e * HID + o0);
    const float4 ga1 = *(const float4*)(g + (size_t)e * HID + o0 + 4);
    const float4 bb0 = *(const float4*)(beta + (size_t)e * HID + o0);
    const float4 bb1 = *(const float4*)(beta + (size_t)e * HID + o0 + 4);
    float y[8];
    y[0] = (v[0] - mu) * rs * ga0.x + bb0.x;
    y[1] = (v[1] - mu) * rs * ga0.y + bb0.y;
    y[2] = (v[2] - mu) * rs * ga0.z + bb0.z;
    y[3] = (v[3] - mu) * rs * ga0.w + bb0.w;
    y[4] = (v[4] - mu) * rs * ga1.x + bb1.x;
    y[5] = (v[5] - mu) * rs * ga1.y + bb1.y;
    y[6] = (v[6] - mu) * rs * ga1.z + bb1.z;
    y[7] = (v[7] - mu) * rs * ga1.w + bb1.w;
    uint32_t lo = 0, hi = 0;
#pragma unroll
    for (int j = 0; j < 4; j++) lo |= (y[j] > 0.f ? FP8_P1 : 0u) << (8 * j);
#pragma unroll
    for (int j = 0; j < 4; j++) hi |= (y[4 + j] > 0.f ? FP8_P1 : 0u) << (8 * j);
    *(uint2*)(out + base + o0) = make_uint2(lo, hi);
}

// ------------------------- router layer3 + softmax top-2 + gates -------------------------
__global__ void router_top2(const float* __restrict__ r2, const float* __restrict__ Wr3,
                            const float* __restrict__ br3, float2* __restrict__ gates,
                            int2* __restrict__ sel) {
    __shared__ float w[NEXP * RH2];
    __shared__ float bsh[NEXP];
    const int tid = threadIdx.x;
    for (int i = tid; i < NEXP * RH2; i += 256) w[i] = Wr3[i];
    if (tid < NEXP) bsh[tid] = br3[tid];
    __syncthreads();
    const int warp = tid >> 5, lane = tid & 31;
    const int token = blockIdx.x * 8 + warp;
    const float* xr = r2 + (size_t)token * RH2;
    float acc[NEXP] = {0.f, 0.f, 0.f, 0.f};
    for (int k = lane; k < RH2; k += 32) {
        const float xv = xr[k];
#pragma unroll
        for (int e = 0; e < NEXP; e++) acc[e] += xv * w[e * RH2 + k];
    }
#pragma unroll
    for (int e = 0; e < NEXP; e++)
#pragma unroll
        for (int off = 16; off; off >>= 1) acc[e] += __shfl_xor_sync(0xffffffffu, acc[e], off);
    if (lane == 0) {
        float sc[NEXP];
#pragma unroll
        for (int e = 0; e < NEXP; e++) sc[e] = acc[e] + bsh[e];
        int i0 = 0; float v0 = sc[0];
#pragma unroll
        for (int e = 1; e < NEXP; e++) if (sc[e] > v0) { v0 = sc[e]; i0 = e; }
        int i1 = -1; float v1 = -1e30f;
#pragma unroll
        for (int e = 0; e < NEXP; e++) if (e != i0 && sc[e] > v1) { v1 = sc[e]; i1 = e; }
        const float t = expf(v1 - v0);
        const float g0 = 1.f / (1.f + t);
        const float g1 = t / (1.f + t);
        gates[token] = make_float2(g0, g1);
        sel[token] = make_int2(i0, i1);
    }
}

// ------------------------- compaction -------------------------
__global__ void reset_cnt(int* __restrict__ cnt) {
    if (threadIdx.x < NEXP) cnt[threadIdx.x] = 0;
}

__global__ void assign_kernel(const int2* __restrict__ sel, int* __restrict__ cnt,
                              int* __restrict__ idx, int2* __restrict__ pos) {
    __shared__ int local[NEXP];
    __shared__ int base[NEXP];
    const int tok = blockIdx.x * 256 + threadIdx.x;
    if (threadIdx.x < NEXP) local[threadIdx.x] = 0;
    __syncthreads();
    const int2 s = sel[tok];
    const int p0 = atomicAdd(&local[s.x], 1);
    const int p1 = atomicAdd(&local[s.y], 1);
    __syncthreads();
    if (threadIdx.x < NEXP) base[threadIdx.x] = atomicAdd(&cnt[threadIdx.x], local[threadIdx.x]);
    __syncthreads();
    const int g0 = base[s.x] + p0, g1 = base[s.y] + p1;
    idx[s.x * B_TOK + g0] = tok;
    idx[s.y * B_TOK + g1] = tok;
    pos[tok] = make_int2(g0, g1);
}

__global__ void padcnt_kernel(const int* __restrict__ cnt, int* __restrict__ padcnt) {
    const int e = threadIdx.x;
    if (e < NEXP) padcnt[e] = ((cnt[e] + 255) / 256) * 256;
}

__global__ void gather_sign_kernel(const float* __restrict__ x, const int* __restrict__ idx,
                                   const int* __restrict__ padcnt, uint8_t* __restrict__ xse) {
    const int e = blockIdx.y, p = blockIdx.x;
    if (p >= __ldg(&padcnt[e])) return;
    const int tok = idx[e * B_TOK + p];
    const float4* src = (const float4*)(x + (size_t)tok * IN_DIM);
    uint32_t* dst = (uint32_t*)(xse + ((size_t)e * B_TOK + p) * IN_DIM);
    for (int i = threadIdx.x; i < IN_DIM / 4; i += 128) {
        const float4 v = src[i];
        uint32_t b;
        b  = (v.x > 0.f ? FP8_P1 : (v.x < 0.f ? FP8_M1 : 0u));
        b |= (v.y > 0.f ? FP8_P1 : (v.y < 0.f ? FP8_M1 : 0u)) << 8;
        b |= (v.z > 0.f ? FP8_P1 : (v.z < 0.f ? FP8_M1 : 0u)) << 16;
        b |= (v.w > 0.f ? FP8_P1 : (v.w < 0.f ? FP8_M1 : 0u)) << 24;
        dst[i] = b;
    }
}

// ------------------------- final gate combine -------------------------
__global__ void combine_kernel(const __half* __restrict__ eo, const float2* __restrict__ gates,
                               const int2* __restrict__ sel, const int2* __restrict__ pos,
                               float* __restrict__ out) {
    const int b = blockIdx.x;
    const float2 g = gates[b];
    const int2 s = sel[b];
    const int2 p = pos[b];
    const __half2* e0 = (const __half2*)(eo + ((size_t)s.x * B_TOK + p.x) * NCLS_PAD);
    const __half2* e1 = (const __half2*)(eo + ((size_t)s.y * B_TOK + p.y) * NCLS_PAD);
    float2* o = (float2*)(out + (size_t)b * NCLS);
    for (int c = threadIdx.x; c < NCLS / 2; c += blockDim.x) {
        const float2 a = __half22float2(e0[c]);
        const float2 bb = __half22float2(e1[c]);
        float2 r;
        r.x = g.x * a.x + g.y * bb.x;
        r.y = g.x * a.y + g.y * bb.y;
        o[c] = r;
    }
}

// ------------------------- launcher -------------------------
extern "C" void kernel_launch(void* const* d_in, const int* in_sizes, int n_in,
                              void* d_out, int out_size) {
    const float* x   = (const float*)d_in[0];
    const float* Wr1 = (const float*)d_in[1];
    const float* br1 = (const float*)d_in[2];
    const float* Wr2 = (const float*)d_in[3];
    const float* br2 = (const float*)d_in[4];
    const float* Wr3 = (const float*)d_in[5];
    const float* br3 = (const float*)d_in[6];
    const float* W1  = (const float*)d_in[7];
    const float* g1  = (const float*)d_in[8];
    const float* b1  = (const float*)d_in[9];
    const float* W2  = (const float*)d_in[10];
    const float* g2  = (const float*)d_in[11];
    const float* b2  = (const float*)d_in[12];
    const float* W3  = (const float*)d_in[13];
    float* out = (float*)d_out;

    __half* h;           cudaGetSymbolAddress((void**)&h, d_h);
    uint8_t* s;          cudaGetSymbolAddress((void**)&s, d_s);
    uint8_t* w1t;        cudaGetSymbolAddress((void**)&w1t, d_w1t);
    uint8_t* w2t;        cudaGetSymbolAddress((void**)&w2t, d_w2t);
    uint8_t* w3t;        cudaGetSymbolAddress((void**)&w3t, d_w3t);
    uint8_t* xse;        cudaGetSymbolAddress((void**)&xse, d_xse);
    __nv_bfloat16* xsp;  cudaGetSymbolAddress((void**)&xsp, d_xsplit);
    __nv_bfloat16* wr1s; cudaGetSymbolAddress((void**)&wr1s, d_wr1s);
    __nv_bfloat16* wr2s; cudaGetSymbolAddress((void**)&wr2s, d_wr2s);
    __nv_bfloat16* r1s;  cudaGetSymbolAddress((void**)&r1s, d_r1s);
    float* r2;           cudaGetSymbolAddress((void**)&r2, d_r2);
    float2* gates;       cudaGetSymbolAddress((void**)&gates, d_gates);
    int2* sel;           cudaGetSymbolAddress((void**)&sel, d_sel);
    int2* pos;           cudaGetSymbolAddress((void**)&pos, d_pos);
    int* cnt;            cudaGetSymbolAddress((void**)&cnt, d_cnt);
    int* padcnt;         cudaGetSymbolAddress((void**)&padcnt, d_padcnt);
    int* idx;            cudaGetSymbolAddress((void**)&idx, d_idx);
    float* wpart;        cudaGetSymbolAddress((void**)&wpart, d_wpart);
    float* wmean;        cudaGetSymbolAddress((void**)&wmean, d_wmean);

    cudaFuncSetAttribute(gemm_fp8_kernel,
                         cudaFuncAttributeMaxDynamicSharedMemorySize, FP8_SMEM);

    // ---- weight ternarization -> e4m3 ----
    wsum_partial<<<dim3(256, NEXP), 256>>>(W1, wpart, (long)HID * IN_DIM / 4);
    wmean_final<<<NEXP, 256>>>(wpart, wmean + 0, (long)HID * IN_DIM, 256);
    ternarize_fp8<<<dim3((HID * IN_DIM / 4 + 255) / 256, NEXP), 256>>>(W1, wmean + 0, w1t, HID, HID, IN_DIM);

    wsum_partial<<<dim3(256, NEXP), 256>>>(W2, wpart, (long)HID * HID / 4);
    wmean_final<<<NEXP, 256>>>(wpart, wmean + 4, (long)HID * HID, 256);
    ternarize_fp8<<<dim3((HID * HID / 4 + 255) / 256, NEXP), 256>>>(W2, wmean + 4, w2t, HID, HID, HID);

    wsum_partial<<<dim3(256, NEXP), 256>>>(W3, wpart, (long)NCLS * HID / 4);
    wmean_final<<<NEXP, 256>>>(wpart, wmean + 8, (long)NCLS * HID, 256);
    ternarize_fp8<<<dim3((NCLS_PAD * HID / 4 + 255) / 256, NEXP), 256>>>(W3, wmean + 8, w3t, NCLS, NCLS_PAD, HID);

    // ---- router prep + GEMMs (split-3 bf16; err ~1e-5) ----
    split3A_kernel<<<(B_TOK * IN_DIM) / 256, 256>>>(x, xsp, (long)B_TOK * IN_DIM);
    split3B_kernel<<<(RH * IN_DIM + 255) / 256, 256>>>(Wr1, wr1s, (long)RH * IN_DIM);
    split3B_kernel<<<(RH2 * RH + 255) / 256, 256>>>(Wr2, wr2s, (long)RH2 * RH);

    gemm_bf16_kernel<2><<<dim3(RH / 64, B_TOK / 128), 256>>>(
        xsp, wr1s, (void*)r1s, RH, IN_DIM * 3, br1);
    gemm_bf16_kernel<1><<<dim3(RH2 / 64, B_TOK / 128), 256>>>(
        r1s, wr2s, (void*)r2, RH2, RH * 3, br2);
    router_top2<<<B_TOK / 8, 256>>>(r2, Wr3, br3, gates, sel);

    // ---- top-2 compaction (padded to 256 rows) ----
    reset_cnt<<<1, 32>>>(cnt);
    assign_kernel<<<B_TOK / 256, 256>>>(sel, cnt, idx, pos);
    padcnt_kernel<<<1, 32>>>(cnt, padcnt);
    gather_sign_kernel<<<dim3(B_TOK, NEXP), 128>>>(x, idx, padcnt, xse);

    // ---- experts (exact ternary e4m3 MMA, f16 accum, 256x256 tiles, 512 thr) ----
    gemm_fp8_kernel<<<dim3(HID / 256, B_TOK / 256, NEXP), 512, FP8_SMEM>>>(
        xse, (size_t)B_TOK * IN_DIM, w1t, (size_t)HID * IN_DIM, h,
        (size_t)B_TOK * HID, HID, IN_DIM, padcnt);
    ln_sign_kernel<<<dim3(B_TOK, NEXP), 256>>>(h, g1, b1, s, padcnt);

    gemm_fp8_kernel<<<dim3(HID / 256, B_TOK / 256, NEXP), 512, FP8_SMEM>>>(
        s, (size_t)B_TOK * HID, w2t, (size_t)HID * HID, h,
        (size_t)B_TOK * HID, HID, HID, padcnt);
    ln_sign_kernel<<<dim3(B_TOK, NEXP), 256>>>(h, g2, b2, s, padcnt);

    gemm_fp8_kernel<<<dim3(NCLS_PAD / 256, B_TOK / 256, NEXP), 512, FP8_SMEM>>>(
        s, (size_t)B_TOK * HID, w3t, (size_t)NCLS_PAD * HID, h,
        (size_t)B_TOK * NCLS_PAD, NCLS_PAD, HID, padcnt);

    // ---- top-2 gate combine ----
    combine_kernel<<<B_TOK, 256>>>(h, gates, sel, pos, out);
}